// round 9
// baseline (speedup 1.0000x reference)
#include <cuda_runtime.h>
#include <cuda_bf16.h>
#include <math.h>
#include <stdint.h>

// ---------------------------------------------------------------------------
// SwinBlock3D: all matmuls on HMMA bf16 m16n8k16 (3-stage cp.async GEMMs,
// bf16 flash attention). x(1,384,16,64,64) GRID=(4,8,8) SHIFT=(2,4,4) HEADS=6
// ---------------------------------------------------------------------------

#define NTOK 65536
#define CDIM 384
#define MLPD 1536

typedef __nv_bfloat16 bf16;
typedef __nv_bfloat162 bf162;

__device__ float g_xw [(size_t)NTOK * CDIM];   // fp32 residual stream
__device__ bf16  g_h  [(size_t)NTOK * CDIM];
__device__ bf16  g_q  [(size_t)NTOK * CDIM];
__device__ bf16  g_k  [(size_t)NTOK * CDIM];
__device__ bf16  g_v  [(size_t)NTOK * CDIM];
__device__ bf16  g_att[(size_t)NTOK * CDIM];
__device__ float g_x2 [(size_t)NTOK * CDIM];
__device__ bf16  g_mlp[(size_t)NTOK * MLPD];
__device__ float g_y  [(size_t)NTOK * CDIM];
__device__ bf16  g_wt [1769472];

// ---------------- helpers ----------------------------------------------------
__device__ __forceinline__ uint32_t smem_u32(const void* p) {
    uint32_t a;
    asm("{ .reg .u64 t; cvta.to.shared.u64 t, %1; cvt.u32.u64 %0, t; }"
        : "=r"(a) : "l"(p));
    return a;
}
__device__ __forceinline__ void cp_async16(uint32_t s, const void* g) {
    asm volatile("cp.async.cg.shared.global [%0], [%1], 16;" :: "r"(s), "l"(g));
}
__device__ __forceinline__ void cp_commit() {
    asm volatile("cp.async.commit_group;");
}
template<int N> __device__ __forceinline__ void cp_wait() {
    asm volatile("cp.async.wait_group %0;" :: "n"(N));
}
__device__ __forceinline__ void ldm_x4(uint32_t r[4], uint32_t addr) {
    asm volatile("ldmatrix.sync.aligned.m8n8.x4.shared.b16 {%0,%1,%2,%3}, [%4];"
                 : "=r"(r[0]), "=r"(r[1]), "=r"(r[2]), "=r"(r[3]) : "r"(addr));
}
__device__ __forceinline__ void ldm_x4_t(uint32_t r[4], uint32_t addr) {
    asm volatile("ldmatrix.sync.aligned.m8n8.x4.trans.shared.b16 {%0,%1,%2,%3}, [%4];"
                 : "=r"(r[0]), "=r"(r[1]), "=r"(r[2]), "=r"(r[3]) : "r"(addr));
}
__device__ __forceinline__ void mma_bf16(float c[4], const uint32_t a[4],
                                         const uint32_t b[2]) {
    asm volatile(
        "mma.sync.aligned.m16n8k16.row.col.f32.bf16.bf16.f32 "
        "{%0,%1,%2,%3}, {%4,%5,%6,%7}, {%8,%9}, {%0,%1,%2,%3};"
        : "+f"(c[0]), "+f"(c[1]), "+f"(c[2]), "+f"(c[3])
        : "r"(a[0]), "r"(a[1]), "r"(a[2]), "r"(a[3]), "r"(b[0]), "r"(b[1]));
}
__device__ __forceinline__ uint2 pack4bf(float4 r) {
    bf162 lo = __floats2bfloat162_rn(r.x, r.y);
    bf162 hi = __floats2bfloat162_rn(r.z, r.w);
    uint2 u;
    u.x = *(uint32_t*)&lo;
    u.y = *(uint32_t*)&hi;
    return u;
}

extern __shared__ char s_dyn[];

// ---------------- weight transpose: dst[n][k] = bf16(src[k][n]) --------------
__global__ void transpose_kernel(const float* __restrict__ src,
                                 bf16* __restrict__ dst, int K, int N) {
    __shared__ float tile[32][33];
    int n0 = blockIdx.x * 32, k0 = blockIdx.y * 32;
    int tx = threadIdx.x & 31, ty = threadIdx.x >> 5;
#pragma unroll
    for (int i = ty; i < 32; i += 8)
        tile[i][tx] = src[(size_t)(k0 + i) * N + n0 + tx];
    __syncthreads();
#pragma unroll
    for (int i = ty; i < 32; i += 8)
        dst[(size_t)(n0 + i) * K + k0 + tx] = __float2bfloat16(tile[tx][i]);
}

// ---------------- shift + window partition -----------------------------------
__device__ __forceinline__ int token_index(int d, int h, int w) {
    int win = ((d >> 2) * 8 + (h >> 3)) * 8 + (w >> 3);
    int tok = ((d & 3) << 6) + ((h & 7) << 3) + (w & 7);
    return (win << 8) + tok;
}

__global__ void window_gather_kernel(const float* __restrict__ x,
                                     float* __restrict__ xw) {
    __shared__ float sm[32][65];
    const int c0 = blockIdx.x * 32;
    const int h0 = blockIdx.y;
    const int d0 = blockIdx.z;
    const int tid = threadIdx.x;
    {
        int cl = tid >> 4;
        int v4 = (tid & 15) * 4;
        const float* xp = x + (size_t)(c0 + cl) * 65536 + d0 * 4096 + h0 * 64 + v4;
        float4 a = *(const float4*)xp;
        sm[cl][v4 + 0] = a.x; sm[cl][v4 + 1] = a.y;
        sm[cl][v4 + 2] = a.z; sm[cl][v4 + 3] = a.w;
        float4 b = *(const float4*)(xp + (size_t)16 * 65536);
        sm[cl + 16][v4 + 0] = b.x; sm[cl + 16][v4 + 1] = b.y;
        sm[cl + 16][v4 + 2] = b.z; sm[cl + 16][v4 + 3] = b.w;
    }
    __syncthreads();
    int w0 = tid >> 2;
    int cg = (tid & 3) * 8;
    int d = (d0 + 14) & 15;
    int h = (h0 + 60) & 63;
    int w = (w0 + 60) & 63;
    int n = token_index(d, h, w);
    float* op = xw + (size_t)n * CDIM + c0 + cg;
    float4 o0, o1;
    o0.x = sm[cg + 0][w0]; o0.y = sm[cg + 1][w0];
    o0.z = sm[cg + 2][w0]; o0.w = sm[cg + 3][w0];
    o1.x = sm[cg + 4][w0]; o1.y = sm[cg + 5][w0];
    o1.z = sm[cg + 6][w0]; o1.w = sm[cg + 7][w0];
    *(float4*)op = o0;
    *(float4*)(op + 4) = o1;
}

__global__ void window_scatter_kernel(const float* __restrict__ y,
                                      float* __restrict__ out) {
    __shared__ float sm[32][65];
    const int c0 = blockIdx.x * 32;
    const int h0 = blockIdx.y;
    const int d0 = blockIdx.z;
    const int tid = threadIdx.x;
    {
        int w0 = tid >> 2;
        int cg = (tid & 3) * 8;
        int d = (d0 + 14) & 15;
        int h = (h0 + 60) & 63;
        int w = (w0 + 60) & 63;
        int n = token_index(d, h, w);
        const float* ip = y + (size_t)n * CDIM + c0 + cg;
        float4 a = *(const float4*)ip;
        float4 b = *(const float4*)(ip + 4);
        sm[cg + 0][w0] = a.x; sm[cg + 1][w0] = a.y;
        sm[cg + 2][w0] = a.z; sm[cg + 3][w0] = a.w;
        sm[cg + 4][w0] = b.x; sm[cg + 5][w0] = b.y;
        sm[cg + 6][w0] = b.z; sm[cg + 7][w0] = b.w;
    }
    __syncthreads();
    int cl = tid >> 4;
    int v4 = (tid & 15) * 4;
    float* op = out + (size_t)(c0 + cl) * 65536 + d0 * 4096 + h0 * 64 + v4;
    float4 o;
    o.x = sm[cl][v4 + 0]; o.y = sm[cl][v4 + 1];
    o.z = sm[cl][v4 + 2]; o.w = sm[cl][v4 + 3];
    *(float4*)op = o;
    float4 p;
    p.x = sm[cl + 16][v4 + 0]; p.y = sm[cl + 16][v4 + 1];
    p.z = sm[cl + 16][v4 + 2]; p.w = sm[cl + 16][v4 + 3];
    *(float4*)(op + (size_t)16 * 65536) = p;
}

// ---------------- layernorm (fp32 in, bf16 out) ------------------------------
__global__ void ln_kernel(const float* __restrict__ x,
                          const float* __restrict__ gam,
                          const float* __restrict__ bet,
                          bf16* __restrict__ out) {
    int warp = threadIdx.x >> 5;
    int lane = threadIdx.x & 31;
    size_t n = (size_t)blockIdx.x * 8 + warp;
    const float4* xr = (const float4*)(x + n * CDIM);
    float4 v[3];
    float s = 0.f, ss = 0.f;
#pragma unroll
    for (int i = 0; i < 3; i++) {
        v[i] = xr[i * 32 + lane];
        s += v[i].x + v[i].y + v[i].z + v[i].w;
        ss += v[i].x * v[i].x + v[i].y * v[i].y + v[i].z * v[i].z + v[i].w * v[i].w;
    }
#pragma unroll
    for (int off = 16; off; off >>= 1) {
        s  += __shfl_xor_sync(0xffffffffu, s,  off);
        ss += __shfl_xor_sync(0xffffffffu, ss, off);
    }
    float mean = s * (1.0f / CDIM);
    float var  = ss * (1.0f / CDIM) - mean * mean;
    float rstd = rsqrtf(var + 1e-5f);
    const float4* G = (const float4*)gam;
    const float4* B = (const float4*)bet;
    uint2* o = (uint2*)(out + n * CDIM);
#pragma unroll
    for (int i = 0; i < 3; i++) {
        float4 g = G[i * 32 + lane];
        float4 b = B[i * 32 + lane];
        float4 r;
        r.x = (v[i].x - mean) * rstd * g.x + b.x;
        r.y = (v[i].y - mean) * rstd * g.y + b.y;
        r.z = (v[i].z - mean) * rstd * g.z + b.z;
        r.w = (v[i].w - mean) * rstd * g.w + b.w;
        o[i * 32 + lane] = pack4bf(r);
    }
}

// ---------------- BF16 GEMM core: 3-stage cp.async, 1 sync/stage -------------
#define RS 24
#define KBLK 3072
#define BUFE 6144
#define GSMEM (6 * BUFE * 2)   // 73728 bytes (sA 3 bufs + sB 3 bufs)

__device__ __forceinline__ void mma_tile(const bf16* __restrict__ A,
                                         const bf16* __restrict__ Bt,
                                         int K, int rowBase, int colBase,
                                         float acc[4][4][4]) {
    bf16* sA = (bf16*)s_dyn;
    bf16* sB = sA + 3 * BUFE;
    const int tid = threadIdx.x;
    const int nk = K >> 5;
    const int wid = tid >> 5, lane = tid & 31;
    const int wr = (wid >> 2) * 64, wc = (wid & 3) * 32;
    const int arow = wr + (lane & 15);
    const int ahalf = (lane >> 4) * 8;
    const int brow = wc + (lane & 7) + ((lane >> 4) << 3);
    const int bhalf = ((lane >> 3) & 1) * 8;

#pragma unroll
    for (int mt = 0; mt < 4; mt++)
#pragma unroll
        for (int nt = 0; nt < 4; nt++)
#pragma unroll
            for (int f = 0; f < 4; f++) acc[mt][nt][f] = 0.f;

    auto stage = [&](int ks, int buf) {
        const bf16* Ap = A + (size_t)rowBase * K + ks * 32;
        const bf16* Bp = Bt + (size_t)colBase * K + ks * 32;
#pragma unroll
        for (int i = 0; i < 2; i++) {
            int c = tid * 2 + i;
            int r = c >> 2, piece = c & 3;
            int kb = piece >> 1, half = piece & 1;
            uint32_t dA = smem_u32(&sA[buf * BUFE + kb * KBLK + r * RS + half * 8]);
            uint32_t dB = smem_u32(&sB[buf * BUFE + kb * KBLK + r * RS + half * 8]);
            cp_async16(dA, Ap + (size_t)r * K + kb * 16 + half * 8);
            cp_async16(dB, Bp + (size_t)r * K + kb * 16 + half * 8);
        }
        cp_commit();
    };

    stage(0, 0);
    stage(1, 1);
    int cur = 0;
    for (int k = 0; k < nk; k++) {
        if (k == nk - 1) cp_wait<0>(); else cp_wait<1>();
        __syncthreads();
        if (k + 2 < nk) {
            int nb = cur + 2; if (nb >= 3) nb -= 3;
            stage(k + 2, nb);
        }
        uint32_t aB = smem_u32(sA + cur * BUFE);
        uint32_t bB = smem_u32(sB + cur * BUFE);
#pragma unroll
        for (int kb = 0; kb < 2; kb++) {
            uint32_t af[4][4], bb[2][4];
#pragma unroll
            for (int mt = 0; mt < 4; mt++)
                ldm_x4(af[mt], aB + (uint32_t)((kb * KBLK +
                         (arow + mt * 16) * RS + ahalf) * 2));
#pragma unroll
            for (int nh = 0; nh < 2; nh++)
                ldm_x4(bb[nh], bB + (uint32_t)((kb * KBLK +
                         (brow + nh * 16) * RS + bhalf) * 2));
#pragma unroll
            for (int mt = 0; mt < 4; mt++)
#pragma unroll
                for (int nt = 0; nt < 4; nt++)
                    mma_bf16(acc[mt][nt], af[mt], &bb[nt >> 1][(nt & 1) * 2]);
        }
        cur++; if (cur == 3) cur = 0;
    }
}

// ---- QKV GEMM: scatter bf16 to [win][head][t][64] ---------------------------
__global__ __launch_bounds__(256, 2)
void mm_qkv(const bf16* __restrict__ hb, const bf16* __restrict__ wt,
            const float* __restrict__ bq, const float* __restrict__ bk,
            const float* __restrict__ bv,
            bf16* __restrict__ q, bf16* __restrict__ k,
            bf16* __restrict__ v) {
    int g = blockIdx.z;
    const bf16* Bt = wt + (size_t)g * 147456;
    const float* bias = (g == 0) ? bq : (g == 1) ? bk : bv;
    bf16* out = (g == 0) ? q : (g == 1) ? k : v;
    int rowBase = blockIdx.y * 128, colBase = blockIdx.x * 128;

    float acc[4][4][4];
    mma_tile(hb, Bt, CDIM, rowBase, colBase, acc);

    const int lane = threadIdx.x & 31, wid = threadIdx.x >> 5;
    const int gid = lane >> 2, tig = lane & 3;
    const int wr = (wid >> 2) * 64, wc = (wid & 3) * 32;
#pragma unroll
    for (int mt = 0; mt < 4; mt++) {
        int r0 = rowBase + wr + mt * 16 + gid;
#pragma unroll
        for (int nt = 0; nt < 4; nt++) {
            int c = colBase + wc + nt * 8 + 2 * tig;
            int head = c >> 6, dd = c & 63;
            float bx = bias[c], by = bias[c + 1];
#pragma unroll
            for (int hh = 0; hh < 2; hh++) {
                int r = r0 + hh * 8;
                int win = r >> 8, t = r & 255;
                bf162 o = __floats2bfloat162_rn(acc[mt][nt][2 * hh] + bx,
                                                acc[mt][nt][2 * hh + 1] + by);
                *(bf162*)(out + (size_t)win * 98304 + head * 16384 +
                          t * 64 + dd) = o;
            }
        }
    }
}

// ---- GEMM + bias + residual (fp32 out) --------------------------------------
__global__ __launch_bounds__(256, 2)
void mm_biasres(const bf16* __restrict__ A, const bf16* __restrict__ Bt,
                const float* __restrict__ bias, const float* __restrict__ res,
                float* __restrict__ out, int K) {
    int rowBase = blockIdx.y * 128, colBase = blockIdx.x * 128;
    float acc[4][4][4];
    mma_tile(A, Bt, K, rowBase, colBase, acc);

    const int lane = threadIdx.x & 31, wid = threadIdx.x >> 5;
    const int gid = lane >> 2, tig = lane & 3;
    const int wr = (wid >> 2) * 64, wc = (wid & 3) * 32;
#pragma unroll
    for (int mt = 0; mt < 4; mt++) {
        int r0 = rowBase + wr + mt * 16 + gid;
#pragma unroll
        for (int nt = 0; nt < 4; nt++) {
            int c = colBase + wc + nt * 8 + 2 * tig;
            float bx = bias[c], by = bias[c + 1];
#pragma unroll
            for (int hh = 0; hh < 2; hh++) {
                size_t off = (size_t)(r0 + hh * 8) * CDIM + c;
                float2 rr = *(const float2*)(res + off);
                float2 o = make_float2(acc[mt][nt][2 * hh] + bx + rr.x,
                                       acc[mt][nt][2 * hh + 1] + by + rr.y);
                *(float2*)(out + off) = o;
            }
        }
    }
}

// ---- GEMM + bias + exact GELU (bf16 out, N=1536) ----------------------------
__device__ __forceinline__ float gelu_f(float v) {
    return 0.5f * v * (1.0f + erff(v * 0.70710678118654752440f));
}

__global__ __launch_bounds__(256, 2)
void mm_gelu(const bf16* __restrict__ A, const bf16* __restrict__ Bt,
             const float* __restrict__ bias, bf16* __restrict__ out) {
    int rowBase = blockIdx.y * 128, colBase = blockIdx.x * 128;
    float acc[4][4][4];
    mma_tile(A, Bt, CDIM, rowBase, colBase, acc);

    const int lane = threadIdx.x & 31, wid = threadIdx.x >> 5;
    const int gid = lane >> 2, tig = lane & 3;
    const int wr = (wid >> 2) * 64, wc = (wid & 3) * 32;
#pragma unroll
    for (int mt = 0; mt < 4; mt++) {
        int r0 = rowBase + wr + mt * 16 + gid;
#pragma unroll
        for (int nt = 0; nt < 4; nt++) {
            int c = colBase + wc + nt * 8 + 2 * tig;
            float bx = bias[c], by = bias[c + 1];
#pragma unroll
            for (int hh = 0; hh < 2; hh++) {
                size_t off = (size_t)(r0 + hh * 8) * MLPD + c;
                bf162 o = __floats2bfloat162_rn(
                    gelu_f(acc[mt][nt][2 * hh] + bx),
                    gelu_f(acc[mt][nt][2 * hh + 1] + by));
                *(bf162*)(out + off) = o;
            }
        }
    }
}

// ---------------- attention: bf16 flash, one CTA per (window, head) ----------
// smem: K[256x88] bf16 | V[256x88] bf16 | P/Q[256x88] bf16 (warp-private P)
#define AST 88
#define ATT_SMEM (3 * 256 * AST * 2)

__global__ __launch_bounds__(256, 1)
void attn_mma(const bf16* __restrict__ q, const bf16* __restrict__ k,
              const bf16* __restrict__ v, bf16* __restrict__ out) {
    bf16* Kb = (bf16*)s_dyn;
    bf16* Vb = Kb + 256 * AST;
    bf16* Pb = Vb + 256 * AST;
    const int wh = blockIdx.x;
    const size_t base = (size_t)wh * 16384;
    const int tid = threadIdx.x;
    const int wid = tid >> 5, lane = tid & 31;
    const int gid = lane >> 2, tig = lane & 3;
    const int qr = wid * 32;
    bf16* Pw = Pb + wid * 32 * AST;
    const uint32_t KbB = smem_u32(Kb), VbB = smem_u32(Vb);
    const uint32_t PwB = smem_u32(Pw), PbB = smem_u32(Pb);

    // stage K, V, Q(scaled by 1/8) rows into smem (bf16)
    {
        const uint4* Kg = (const uint4*)(k + base + (size_t)tid * 64);
        const uint4* Vg = (const uint4*)(v + base + (size_t)tid * 64);
        const uint4* Qg = (const uint4*)(q + base + (size_t)tid * 64);
        uint4* Kd = (uint4*)(Kb + tid * AST);
        uint4* Vd = (uint4*)(Vb + tid * AST);
        uint4* Qd = (uint4*)(Pb + tid * AST);
        bf162 sc = __float2bfloat162_rn(0.125f);
#pragma unroll
        for (int i = 0; i < 8; i++) {
            Kd[i] = Kg[i];
            Vd[i] = Vg[i];
            uint4 t = Qg[i];
            bf162* tp = (bf162*)&t;
#pragma unroll
            for (int j = 0; j < 4; j++) tp[j] = __hmul2(tp[j], sc);
            Qd[i] = t;
        }
    }
    __syncthreads();

    // Q A-fragments (k16 x 4 covering dh=64)
    uint32_t qf[2][4][4];
#pragma unroll
    for (int mt = 0; mt < 2; mt++)
#pragma unroll
        for (int ks = 0; ks < 4; ks++)
            ldm_x4(qf[mt][ks], PbB + (uint32_t)(((qr + mt * 16 + (lane & 15)) * AST +
                     ks * 16 + (lane >> 4) * 8) * 2));
    __syncthreads();   // Pb now free -> P scratch

    float oacc[2][8][4];
#pragma unroll
    for (int mt = 0; mt < 2; mt++)
#pragma unroll
        for (int nt = 0; nt < 8; nt++)
#pragma unroll
            for (int f = 0; f < 4; f++) oacc[mt][nt][f] = 0.f;
    float mrow[2][2] = {{-1e30f, -1e30f}, {-1e30f, -1e30f}};
    float lrow[2][2] = {{0.f, 0.f}, {0.f, 0.f}};

    const int kbrow = (lane & 7) + ((lane >> 4) << 3);   // B-frag row pattern
    const int kbhalf = ((lane >> 3) & 1) * 8;
    const int vrow = (lane & 7) + (((lane >> 3) & 1) << 3);  // trans-B row
    const int vdim = (lane >> 4) * 8;

    for (int jb = 0; jb < 4; jb++) {
        // ---- S = Q @ K_jb^T (bf16 mma) ----
        float sacc[2][8][4];
#pragma unroll
        for (int mt = 0; mt < 2; mt++)
#pragma unroll
            for (int nt = 0; nt < 8; nt++)
#pragma unroll
                for (int f = 0; f < 4; f++) sacc[mt][nt][f] = 0.f;
#pragma unroll
        for (int ks = 0; ks < 4; ks++) {
            uint32_t kb4[4][4];
#pragma unroll
            for (int np = 0; np < 4; np++)
                ldm_x4(kb4[np], KbB + (uint32_t)(((jb * 64 + np * 16 + kbrow) * AST +
                         ks * 16 + kbhalf) * 2));
#pragma unroll
            for (int mt = 0; mt < 2; mt++)
#pragma unroll
                for (int nt = 0; nt < 8; nt++)
                    mma_bf16(sacc[mt][nt], qf[mt][ks], &kb4[nt >> 1][(nt & 1) * 2]);
        }

        // ---- online softmax; P -> bf16 in warp-private smem ----
        __syncwarp();
#pragma unroll
        for (int mt = 0; mt < 2; mt++)
#pragma unroll
            for (int hh = 0; hh < 2; hh++) {
                float bm = -1e30f;
#pragma unroll
                for (int nt = 0; nt < 8; nt++) {
                    bm = fmaxf(bm, sacc[mt][nt][2 * hh]);
                    bm = fmaxf(bm, sacc[mt][nt][2 * hh + 1]);
                }
                bm = fmaxf(bm, __shfl_xor_sync(0xffffffffu, bm, 1));
                bm = fmaxf(bm, __shfl_xor_sync(0xffffffffu, bm, 2));
                float mn = fmaxf(mrow[mt][hh], bm);
                float scale = __expf(mrow[mt][hh] - mn);
                mrow[mt][hh] = mn;
                lrow[mt][hh] *= scale;
#pragma unroll
                for (int nt = 0; nt < 8; nt++) {
                    oacc[mt][nt][2 * hh]     *= scale;
                    oacc[mt][nt][2 * hh + 1] *= scale;
                }
                float psum = 0.f;
                int row = mt * 16 + gid + hh * 8;
#pragma unroll
                for (int nt = 0; nt < 8; nt++) {
                    float p0 = __expf(sacc[mt][nt][2 * hh]     - mn);
                    float p1 = __expf(sacc[mt][nt][2 * hh + 1] - mn);
                    psum += p0 + p1;
                    *(bf162*)(Pw + row * AST + nt * 8 + 2 * tig) =
                        __floats2bfloat162_rn(p0, p1);
                }
                psum += __shfl_xor_sync(0xffffffffu, psum, 1);
                psum += __shfl_xor_sync(0xffffffffu, psum, 2);
                lrow[mt][hh] += psum;
            }
        __syncwarp();

        // ---- O += P @ V_jb (bf16 mma, V via trans ldmatrix) ----
#pragma unroll
        for (int ks = 0; ks < 4; ks++) {
            uint32_t pf[2][4], vb4[4][4];
#pragma unroll
            for (int mt = 0; mt < 2; mt++)
                ldm_x4(pf[mt], PwB + (uint32_t)(((mt * 16 + (lane & 15)) * AST +
                         ks * 16 + (lane >> 4) * 8) * 2));
#pragma unroll
            for (int nb = 0; nb < 4; nb++)
                ldm_x4_t(vb4[nb], VbB + (uint32_t)(((jb * 64 + ks * 16 + vrow) * AST +
                           nb * 16 + vdim) * 2));
#pragma unroll
            for (int mt = 0; mt < 2; mt++)
#pragma unroll
                for (int nt = 0; nt < 8; nt++)
                    mma_bf16(oacc[mt][nt], pf[mt], &vb4[nt >> 1][(nt & 1) * 2]);
        }
    }

    // ---- epilogue: normalize, bf16 token-major out ----
    const int win = wh / 6, head = wh % 6;
#pragma unroll
    for (int mt = 0; mt < 2; mt++)
#pragma unroll
        for (int hh = 0; hh < 2; hh++) {
            float inv = 1.0f / lrow[mt][hh];
            int row = qr + mt * 16 + gid + hh * 8;
            bf16* op = out + ((size_t)win * 256 + row) * CDIM + head * 64;
#pragma unroll
            for (int nt = 0; nt < 8; nt++) {
                bf162 o = __floats2bfloat162_rn(
                    oacc[mt][nt][2 * hh] * inv,
                    oacc[mt][nt][2 * hh + 1] * inv);
                *(bf162*)(op + nt * 8 + 2 * tig) = o;
            }
        }
}

// ---------------------------------------------------------------------------
extern "C" void kernel_launch(void* const* d_in, const int* in_sizes, int n_in,
                              void* d_out, int out_size) {
    (void)in_sizes; (void)n_in; (void)out_size;
    const float* x   = (const float*)d_in[0];
    const float* Wq  = (const float*)d_in[1];
    const float* bq  = (const float*)d_in[2];
    const float* Wk  = (const float*)d_in[3];
    const float* bk  = (const float*)d_in[4];
    const float* Wv  = (const float*)d_in[5];
    const float* bv  = (const float*)d_in[6];
    const float* Wo  = (const float*)d_in[7];
    const float* bo  = (const float*)d_in[8];
    const float* g1  = (const float*)d_in[9];
    const float* be1 = (const float*)d_in[10];
    const float* g2  = (const float*)d_in[11];
    const float* be2 = (const float*)d_in[12];
    const float* W1  = (const float*)d_in[13];
    const float* B1  = (const float*)d_in[14];
    const float* W2  = (const float*)d_in[15];
    const float* B2  = (const float*)d_in[16];
    float* out = (float*)d_out;

    float *xw, *x2, *yb;
    bf16 *hb, *qb, *kb, *vb, *att, *mlp, *wt;
    cudaGetSymbolAddress((void**)&xw,  g_xw);
    cudaGetSymbolAddress((void**)&hb,  g_h);
    cudaGetSymbolAddress((void**)&qb,  g_q);
    cudaGetSymbolAddress((void**)&kb,  g_k);
    cudaGetSymbolAddress((void**)&vb,  g_v);
    cudaGetSymbolAddress((void**)&att, g_att);
    cudaGetSymbolAddress((void**)&x2,  g_x2);
    cudaGetSymbolAddress((void**)&mlp, g_mlp);
    cudaGetSymbolAddress((void**)&yb,  g_y);
    cudaGetSymbolAddress((void**)&wt,  g_wt);

    cudaFuncSetAttribute(mm_qkv,
                         cudaFuncAttributeMaxDynamicSharedMemorySize, GSMEM);
    cudaFuncSetAttribute(mm_biasres,
                         cudaFuncAttributeMaxDynamicSharedMemorySize, GSMEM);
    cudaFuncSetAttribute(mm_gelu,
                         cudaFuncAttributeMaxDynamicSharedMemorySize, GSMEM);
    cudaFuncSetAttribute(attn_mma,
                         cudaFuncAttributeMaxDynamicSharedMemorySize, ATT_SMEM);

    // launches 1-5 (ncu -s 5 skips these; #6 = mm_qkv gets profiled)
    transpose_kernel<<<dim3(12, 12), 256>>>(Wq, wt + 0,       CDIM, CDIM);
    transpose_kernel<<<dim3(12, 12), 256>>>(Wk, wt + 147456,  CDIM, CDIM);
    transpose_kernel<<<dim3(12, 12), 256>>>(Wv, wt + 294912,  CDIM, CDIM);
    window_gather_kernel<<<dim3(12, 64, 16), 256>>>(x, xw);
    ln_kernel<<<8192, 256>>>(xw, g1, be1, hb);
    // 6) QKV projections
    mm_qkv<<<dim3(3, 512, 3), 256, GSMEM>>>(hb, wt, bq, bk, bv, qb, kb, vb);
    // remaining transposes (independent of qkv outputs)
    transpose_kernel<<<dim3(12, 12), 256>>>(Wo, wt + 442368,  CDIM, CDIM);
    transpose_kernel<<<dim3(48, 12), 256>>>(W1, wt + 589824,  CDIM, MLPD);
    transpose_kernel<<<dim3(12, 48), 256>>>(W2, wt + 1179648, MLPD, CDIM);
    // windowed attention (bf16 flash)
    attn_mma<<<1536, 256, ATT_SMEM>>>(qb, kb, vb, att);
    // output projection + residual
    mm_biasres<<<dim3(3, 512), 256, GSMEM>>>(att, wt + 442368, bo, xw, x2, CDIM);
    // LN2
    ln_kernel<<<8192, 256>>>(x2, g2, be2, hb);
    // MLP up + GELU
    mm_gelu<<<dim3(12, 512), 256, GSMEM>>>(hb, wt + 589824, B1, mlp);
    // MLP down + residual
    mm_biasres<<<dim3(3, 512), 256, GSMEM>>>(mlp, wt + 1179648, B2, x2, yb, MLPD);
    // reverse window partition + shift
    window_scatter_kernel<<<dim3(12, 64, 16), 256>>>(yb, out);
}

// round 10
// speedup vs baseline: 1.4896x; 1.4896x over previous
#include <cuda_runtime.h>
#include <cuda_bf16.h>
#include <math.h>
#include <stdint.h>

// ---------------------------------------------------------------------------
// SwinBlock3D: GEMMs via mma.sync BF16 (R7-proven 2-stage core), attention
// via bf16 flash mma. x(1,384,16,64,64) GRID=(4,8,8) SHIFT=(2,4,4) HEADS=6
// ---------------------------------------------------------------------------

#define NTOK 65536
#define CDIM 384
#define MLPD 1536

typedef __nv_bfloat16 bf16;
typedef __nv_bfloat162 bf162;

__device__ float g_xw [(size_t)NTOK * CDIM];   // fp32 residual stream
__device__ bf16  g_h  [(size_t)NTOK * CDIM];
__device__ bf16  g_q  [(size_t)NTOK * CDIM];
__device__ bf16  g_k  [(size_t)NTOK * CDIM];
__device__ bf16  g_v  [(size_t)NTOK * CDIM];
__device__ bf16  g_att[(size_t)NTOK * CDIM];
__device__ float g_x2 [(size_t)NTOK * CDIM];
__device__ bf16  g_mlp[(size_t)NTOK * MLPD];
__device__ float g_y  [(size_t)NTOK * CDIM];
__device__ bf16  g_wt [1769472];

// ---------------- helpers ----------------------------------------------------
__device__ __forceinline__ uint32_t smem_u32(const void* p) {
    uint32_t a;
    asm("{ .reg .u64 t; cvta.to.shared.u64 t, %1; cvt.u32.u64 %0, t; }"
        : "=r"(a) : "l"(p));
    return a;
}
__device__ __forceinline__ void cp_async16(uint32_t s, const void* g) {
    asm volatile("cp.async.cg.shared.global [%0], [%1], 16;" :: "r"(s), "l"(g));
}
__device__ __forceinline__ void cp_commit() {
    asm volatile("cp.async.commit_group;");
}
template<int N> __device__ __forceinline__ void cp_wait() {
    asm volatile("cp.async.wait_group %0;" :: "n"(N));
}
__device__ __forceinline__ void ldm_x4(uint32_t r[4], uint32_t addr) {
    asm volatile("ldmatrix.sync.aligned.m8n8.x4.shared.b16 {%0,%1,%2,%3}, [%4];"
                 : "=r"(r[0]), "=r"(r[1]), "=r"(r[2]), "=r"(r[3]) : "r"(addr));
}
__device__ __forceinline__ void ldm_x4_t(uint32_t r[4], uint32_t addr) {
    asm volatile("ldmatrix.sync.aligned.m8n8.x4.trans.shared.b16 {%0,%1,%2,%3}, [%4];"
                 : "=r"(r[0]), "=r"(r[1]), "=r"(r[2]), "=r"(r[3]) : "r"(addr));
}
__device__ __forceinline__ void mma_bf16(float c[4], const uint32_t a[4],
                                         const uint32_t b[2]) {
    asm volatile(
        "mma.sync.aligned.m16n8k16.row.col.f32.bf16.bf16.f32 "
        "{%0,%1,%2,%3}, {%4,%5,%6,%7}, {%8,%9}, {%0,%1,%2,%3};"
        : "+f"(c[0]), "+f"(c[1]), "+f"(c[2]), "+f"(c[3])
        : "r"(a[0]), "r"(a[1]), "r"(a[2]), "r"(a[3]), "r"(b[0]), "r"(b[1]));
}
__device__ __forceinline__ uint2 pack4bf(float4 r) {
    bf162 lo = __floats2bfloat162_rn(r.x, r.y);
    bf162 hi = __floats2bfloat162_rn(r.z, r.w);
    uint2 u;
    u.x = *(uint32_t*)&lo;
    u.y = *(uint32_t*)&hi;
    return u;
}

// ---------------- weight transpose: dst[n][k] = bf16(src[k][n]) --------------
__global__ void transpose_kernel(const float* __restrict__ src,
                                 bf16* __restrict__ dst, int K, int N) {
    __shared__ float tile[32][33];
    int n0 = blockIdx.x * 32, k0 = blockIdx.y * 32;
    int tx = threadIdx.x & 31, ty = threadIdx.x >> 5;
#pragma unroll
    for (int i = ty; i < 32; i += 8)
        tile[i][tx] = src[(size_t)(k0 + i) * N + n0 + tx];
    __syncthreads();
#pragma unroll
    for (int i = ty; i < 32; i += 8)
        dst[(size_t)(n0 + i) * K + k0 + tx] = __float2bfloat16(tile[tx][i]);
}

// ---------------- shift + window partition -----------------------------------
__device__ __forceinline__ int token_index(int d, int h, int w) {
    int win = ((d >> 2) * 8 + (h >> 3)) * 8 + (w >> 3);
    int tok = ((d & 3) << 6) + ((h & 7) << 3) + (w & 7);
    return (win << 8) + tok;
}

__global__ void window_gather_kernel(const float* __restrict__ x,
                                     float* __restrict__ xw) {
    __shared__ float sm[32][65];
    const int c0 = blockIdx.x * 32;
    const int h0 = blockIdx.y;
    const int d0 = blockIdx.z;
    const int tid = threadIdx.x;
    {
        int cl = tid >> 4;
        int v4 = (tid & 15) * 4;
        const float* xp = x + (size_t)(c0 + cl) * 65536 + d0 * 4096 + h0 * 64 + v4;
        float4 a = *(const float4*)xp;
        sm[cl][v4 + 0] = a.x; sm[cl][v4 + 1] = a.y;
        sm[cl][v4 + 2] = a.z; sm[cl][v4 + 3] = a.w;
        float4 b = *(const float4*)(xp + (size_t)16 * 65536);
        sm[cl + 16][v4 + 0] = b.x; sm[cl + 16][v4 + 1] = b.y;
        sm[cl + 16][v4 + 2] = b.z; sm[cl + 16][v4 + 3] = b.w;
    }
    __syncthreads();
    int w0 = tid >> 2;
    int cg = (tid & 3) * 8;
    int d = (d0 + 14) & 15;
    int h = (h0 + 60) & 63;
    int w = (w0 + 60) & 63;
    int n = token_index(d, h, w);
    float* op = xw + (size_t)n * CDIM + c0 + cg;
    float4 o0, o1;
    o0.x = sm[cg + 0][w0]; o0.y = sm[cg + 1][w0];
    o0.z = sm[cg + 2][w0]; o0.w = sm[cg + 3][w0];
    o1.x = sm[cg + 4][w0]; o1.y = sm[cg + 5][w0];
    o1.z = sm[cg + 6][w0]; o1.w = sm[cg + 7][w0];
    *(float4*)op = o0;
    *(float4*)(op + 4) = o1;
}

__global__ void window_scatter_kernel(const float* __restrict__ y,
                                      float* __restrict__ out) {
    __shared__ float sm[32][65];
    const int c0 = blockIdx.x * 32;
    const int h0 = blockIdx.y;
    const int d0 = blockIdx.z;
    const int tid = threadIdx.x;
    {
        int w0 = tid >> 2;
        int cg = (tid & 3) * 8;
        int d = (d0 + 14) & 15;
        int h = (h0 + 60) & 63;
        int w = (w0 + 60) & 63;
        int n = token_index(d, h, w);
        const float* ip = y + (size_t)n * CDIM + c0 + cg;
        float4 a = *(const float4*)ip;
        float4 b = *(const float4*)(ip + 4);
        sm[cg + 0][w0] = a.x; sm[cg + 1][w0] = a.y;
        sm[cg + 2][w0] = a.z; sm[cg + 3][w0] = a.w;
        sm[cg + 4][w0] = b.x; sm[cg + 5][w0] = b.y;
        sm[cg + 6][w0] = b.z; sm[cg + 7][w0] = b.w;
    }
    __syncthreads();
    int cl = tid >> 4;
    int v4 = (tid & 15) * 4;
    float* op = out + (size_t)(c0 + cl) * 65536 + d0 * 4096 + h0 * 64 + v4;
    float4 o;
    o.x = sm[cl][v4 + 0]; o.y = sm[cl][v4 + 1];
    o.z = sm[cl][v4 + 2]; o.w = sm[cl][v4 + 3];
    *(float4*)op = o;
    float4 p;
    p.x = sm[cl + 16][v4 + 0]; p.y = sm[cl + 16][v4 + 1];
    p.z = sm[cl + 16][v4 + 2]; p.w = sm[cl + 16][v4 + 3];
    *(float4*)(op + (size_t)16 * 65536) = p;
}

// ---------------- layernorm (fp32 in, bf16 out) ------------------------------
__global__ void ln_kernel(const float* __restrict__ x,
                          const float* __restrict__ gam,
                          const float* __restrict__ bet,
                          bf16* __restrict__ out) {
    int warp = threadIdx.x >> 5;
    int lane = threadIdx.x & 31;
    size_t n = (size_t)blockIdx.x * 8 + warp;
    const float4* xr = (const float4*)(x + n * CDIM);
    float4 v[3];
    float s = 0.f, ss = 0.f;
#pragma unroll
    for (int i = 0; i < 3; i++) {
        v[i] = xr[i * 32 + lane];
        s += v[i].x + v[i].y + v[i].z + v[i].w;
        ss += v[i].x * v[i].x + v[i].y * v[i].y + v[i].z * v[i].z + v[i].w * v[i].w;
    }
#pragma unroll
    for (int off = 16; off; off >>= 1) {
        s  += __shfl_xor_sync(0xffffffffu, s,  off);
        ss += __shfl_xor_sync(0xffffffffu, ss, off);
    }
    float mean = s * (1.0f / CDIM);
    float var  = ss * (1.0f / CDIM) - mean * mean;
    float rstd = rsqrtf(var + 1e-5f);
    const float4* G = (const float4*)gam;
    const float4* B = (const float4*)bet;
    uint2* o = (uint2*)(out + n * CDIM);
#pragma unroll
    for (int i = 0; i < 3; i++) {
        float4 g = G[i * 32 + lane];
        float4 b = B[i * 32 + lane];
        float4 r;
        r.x = (v[i].x - mean) * rstd * g.x + b.x;
        r.y = (v[i].y - mean) * rstd * g.y + b.y;
        r.z = (v[i].z - mean) * rstd * g.z + b.z;
        r.w = (v[i].w - mean) * rstd * g.w + b.w;
        o[i * 32 + lane] = pack4bf(r);
    }
}

// ---------------- BF16 mma.sync GEMM core (R7: 2-stage, static smem) ---------
#define RS 24
#define KBLK 3072
#define BUFE 6144

__device__ __forceinline__ void mma_tile(const bf16* __restrict__ A,
                                         const bf16* __restrict__ Bt,
                                         int K, int rowBase, int colBase,
                                         float acc[4][4][4]) {
    __shared__ __align__(16) bf16 sA[2 * BUFE];
    __shared__ __align__(16) bf16 sB[2 * BUFE];
    const int tid = threadIdx.x;
    const int nk = K >> 5;
    const int wid = tid >> 5, lane = tid & 31;
    const int wr = (wid >> 2) * 64, wc = (wid & 3) * 32;
    const int arow = wr + (lane & 15);
    const int ahalf = (lane >> 4) * 8;
    const int brow = wc + (lane & 7) + ((lane >> 4) << 3);
    const int bhalf = ((lane >> 3) & 1) * 8;

#pragma unroll
    for (int mt = 0; mt < 4; mt++)
#pragma unroll
        for (int nt = 0; nt < 4; nt++)
#pragma unroll
            for (int f = 0; f < 4; f++) acc[mt][nt][f] = 0.f;

    auto stage = [&](int ks, int buf) {
        const bf16* Ap = A + (size_t)rowBase * K + ks * 32;
        const bf16* Bp = Bt + (size_t)colBase * K + ks * 32;
#pragma unroll
        for (int i = 0; i < 2; i++) {
            int c = tid * 2 + i;
            int r = c >> 2, piece = c & 3;
            int kb = piece >> 1, half = piece & 1;
            uint32_t dA = smem_u32(&sA[buf * BUFE + kb * KBLK + r * RS + half * 8]);
            uint32_t dB = smem_u32(&sB[buf * BUFE + kb * KBLK + r * RS + half * 8]);
            cp_async16(dA, Ap + (size_t)r * K + kb * 16 + half * 8);
            cp_async16(dB, Bp + (size_t)r * K + kb * 16 + half * 8);
        }
        cp_commit();
    };

    stage(0, 0);
    for (int k = 0; k < nk; k++) {
        int cur = k & 1;
        if (k + 1 < nk) { stage(k + 1, cur ^ 1); cp_wait<1>(); }
        else            { cp_wait<0>(); }
        __syncthreads();
        uint32_t aB = smem_u32(sA + cur * BUFE);
        uint32_t bB = smem_u32(sB + cur * BUFE);
#pragma unroll
        for (int kb = 0; kb < 2; kb++) {
            uint32_t af[4][4], bb[2][4];
#pragma unroll
            for (int mt = 0; mt < 4; mt++)
                ldm_x4(af[mt], aB + (uint32_t)((kb * KBLK +
                         (arow + mt * 16) * RS + ahalf) * 2));
#pragma unroll
            for (int nh = 0; nh < 2; nh++)
                ldm_x4(bb[nh], bB + (uint32_t)((kb * KBLK +
                         (brow + nh * 16) * RS + bhalf) * 2));
#pragma unroll
            for (int mt = 0; mt < 4; mt++)
#pragma unroll
                for (int nt = 0; nt < 4; nt++)
                    mma_bf16(acc[mt][nt], af[mt], &bb[nt >> 1][(nt & 1) * 2]);
        }
        __syncthreads();
    }
}

// ---- QKV GEMM: scatter bf16 to [win][head][t][64] ---------------------------
__global__ __launch_bounds__(256, 2)
void mm_qkv(const bf16* __restrict__ hb, const bf16* __restrict__ wt,
            const float* __restrict__ bq, const float* __restrict__ bk,
            const float* __restrict__ bv,
            bf16* __restrict__ q, bf16* __restrict__ k,
            bf16* __restrict__ v) {
    int g = blockIdx.z;
    const bf16* Bt = wt + (size_t)g * 147456;
    const float* bias = (g == 0) ? bq : (g == 1) ? bk : bv;
    bf16* out = (g == 0) ? q : (g == 1) ? k : v;
    int rowBase = blockIdx.y * 128, colBase = blockIdx.x * 128;

    float acc[4][4][4];
    mma_tile(hb, Bt, CDIM, rowBase, colBase, acc);

    const int lane = threadIdx.x & 31, wid = threadIdx.x >> 5;
    const int gid = lane >> 2, tig = lane & 3;
    const int wr = (wid >> 2) * 64, wc = (wid & 3) * 32;
#pragma unroll
    for (int mt = 0; mt < 4; mt++) {
        int r0 = rowBase + wr + mt * 16 + gid;
#pragma unroll
        for (int nt = 0; nt < 4; nt++) {
            int c = colBase + wc + nt * 8 + 2 * tig;
            int head = c >> 6, dd = c & 63;
            float bx = bias[c], by = bias[c + 1];
#pragma unroll
            for (int hh = 0; hh < 2; hh++) {
                int r = r0 + hh * 8;
                int win = r >> 8, t = r & 255;
                bf162 o = __floats2bfloat162_rn(acc[mt][nt][2 * hh] + bx,
                                                acc[mt][nt][2 * hh + 1] + by);
                *(bf162*)(out + (size_t)win * 98304 + head * 16384 +
                          t * 64 + dd) = o;
            }
        }
    }
}

// ---- GEMM + bias + residual (fp32 out) --------------------------------------
__global__ __launch_bounds__(256, 2)
void mm_biasres(const bf16* __restrict__ A, const bf16* __restrict__ Bt,
                const float* __restrict__ bias, const float* __restrict__ res,
                float* __restrict__ out, int K) {
    int rowBase = blockIdx.y * 128, colBase = blockIdx.x * 128;
    float acc[4][4][4];
    mma_tile(A, Bt, K, rowBase, colBase, acc);

    const int lane = threadIdx.x & 31, wid = threadIdx.x >> 5;
    const int gid = lane >> 2, tig = lane & 3;
    const int wr = (wid >> 2) * 64, wc = (wid & 3) * 32;
#pragma unroll
    for (int mt = 0; mt < 4; mt++) {
        int r0 = rowBase + wr + mt * 16 + gid;
#pragma unroll
        for (int nt = 0; nt < 4; nt++) {
            int c = colBase + wc + nt * 8 + 2 * tig;
            float bx = bias[c], by = bias[c + 1];
#pragma unroll
            for (int hh = 0; hh < 2; hh++) {
                size_t off = (size_t)(r0 + hh * 8) * CDIM + c;
                float2 rr = *(const float2*)(res + off);
                float2 o = make_float2(acc[mt][nt][2 * hh] + bx + rr.x,
                                       acc[mt][nt][2 * hh + 1] + by + rr.y);
                *(float2*)(out + off) = o;
            }
        }
    }
}

// ---- GEMM + bias + exact GELU (bf16 out, N=1536) ----------------------------
__device__ __forceinline__ float gelu_f(float v) {
    return 0.5f * v * (1.0f + erff(v * 0.70710678118654752440f));
}

__global__ __launch_bounds__(256, 2)
void mm_gelu(const bf16* __restrict__ A, const bf16* __restrict__ Bt,
             const float* __restrict__ bias, bf16* __restrict__ out) {
    int rowBase = blockIdx.y * 128, colBase = blockIdx.x * 128;
    float acc[4][4][4];
    mma_tile(A, Bt, CDIM, rowBase, colBase, acc);

    const int lane = threadIdx.x & 31, wid = threadIdx.x >> 5;
    const int gid = lane >> 2, tig = lane & 3;
    const int wr = (wid >> 2) * 64, wc = (wid & 3) * 32;
#pragma unroll
    for (int mt = 0; mt < 4; mt++) {
        int r0 = rowBase + wr + mt * 16 + gid;
#pragma unroll
        for (int nt = 0; nt < 4; nt++) {
            int c = colBase + wc + nt * 8 + 2 * tig;
            float bx = bias[c], by = bias[c + 1];
#pragma unroll
            for (int hh = 0; hh < 2; hh++) {
                size_t off = (size_t)(r0 + hh * 8) * MLPD + c;
                bf162 o = __floats2bfloat162_rn(
                    gelu_f(acc[mt][nt][2 * hh] + bx),
                    gelu_f(acc[mt][nt][2 * hh + 1] + by));
                *(bf162*)(out + off) = o;
            }
        }
    }
}

// ---------------- attention: bf16 flash, one CTA per (window, head) ----------
// smem: K[256x88] bf16 | V[256x88] bf16 | P/Q[256x88] bf16 (warp-private P)
#define AST 88
#define ATT_SMEM (3 * 256 * AST * 2)

extern __shared__ char s_dyn[];

__global__ __launch_bounds__(256, 1)
void attn_mma(const bf16* __restrict__ q, const bf16* __restrict__ k,
              const bf16* __restrict__ v, bf16* __restrict__ out) {
    bf16* Kb = (bf16*)s_dyn;
    bf16* Vb = Kb + 256 * AST;
    bf16* Pb = Vb + 256 * AST;
    const int wh = blockIdx.x;
    const size_t base = (size_t)wh * 16384;
    const int tid = threadIdx.x;
    const int wid = tid >> 5, lane = tid & 31;
    const int gid = lane >> 2, tig = lane & 3;
    const int qr = wid * 32;
    bf16* Pw = Pb + wid * 32 * AST;
    const uint32_t KbB = smem_u32(Kb), VbB = smem_u32(Vb);
    const uint32_t PwB = smem_u32(Pw), PbB = smem_u32(Pb);

    // stage K, V, Q(scaled by 1/8) rows into smem (bf16)
    {
        const uint4* Kg = (const uint4*)(k + base + (size_t)tid * 64);
        const uint4* Vg = (const uint4*)(v + base + (size_t)tid * 64);
        const uint4* Qg = (const uint4*)(q + base + (size_t)tid * 64);
        uint4* Kd = (uint4*)(Kb + tid * AST);
        uint4* Vd = (uint4*)(Vb + tid * AST);
        uint4* Qd = (uint4*)(Pb + tid * AST);
        bf162 sc = __float2bfloat162_rn(0.125f);
#pragma unroll
        for (int i = 0; i < 8; i++) {
            Kd[i] = Kg[i];
            Vd[i] = Vg[i];
            uint4 t = Qg[i];
            bf162* tp = (bf162*)&t;
#pragma unroll
            for (int j = 0; j < 4; j++) tp[j] = __hmul2(tp[j], sc);
            Qd[i] = t;
        }
    }
    __syncthreads();

    // Q A-fragments (k16 x 4 covering dh=64)
    uint32_t qf[2][4][4];
#pragma unroll
    for (int mt = 0; mt < 2; mt++)
#pragma unroll
        for (int ks = 0; ks < 4; ks++)
            ldm_x4(qf[mt][ks], PbB + (uint32_t)(((qr + mt * 16 + (lane & 15)) * AST +
                     ks * 16 + (lane >> 4) * 8) * 2));
    __syncthreads();   // Pb now free -> P scratch

    float oacc[2][8][4];
#pragma unroll
    for (int mt = 0; mt < 2; mt++)
#pragma unroll
        for (int nt = 0; nt < 8; nt++)
#pragma unroll
            for (int f = 0; f < 4; f++) oacc[mt][nt][f] = 0.f;
    float mrow[2][2] = {{-1e30f, -1e30f}, {-1e30f, -1e30f}};
    float lrow[2][2] = {{0.f, 0.f}, {0.f, 0.f}};

    const int kbrow = (lane & 7) + ((lane >> 4) << 3);
    const int kbhalf = ((lane >> 3) & 1) * 8;
    const int vrow = (lane & 7) + (((lane >> 3) & 1) << 3);
    const int vdim = (lane >> 4) * 8;

    for (int jb = 0; jb < 4; jb++) {
        // ---- S = Q @ K_jb^T ----
        float sacc[2][8][4];
#pragma unroll
        for (int mt = 0; mt < 2; mt++)
#pragma unroll
            for (int nt = 0; nt < 8; nt++)
#pragma unroll
                for (int f = 0; f < 4; f++) sacc[mt][nt][f] = 0.f;
#pragma unroll
        for (int ks = 0; ks < 4; ks++) {
            uint32_t kb4[4][4];
#pragma unroll
            for (int np = 0; np < 4; np++)
                ldm_x4(kb4[np], KbB + (uint32_t)(((jb * 64 + np * 16 + kbrow) * AST +
                         ks * 16 + kbhalf) * 2));
#pragma unroll
            for (int mt = 0; mt < 2; mt++)
#pragma unroll
                for (int nt = 0; nt < 8; nt++)
                    mma_bf16(sacc[mt][nt], qf[mt][ks], &kb4[nt >> 1][(nt & 1) * 2]);
        }

        // ---- online softmax; P -> bf16 in warp-private smem ----
        __syncwarp();
#pragma unroll
        for (int mt = 0; mt < 2; mt++)
#pragma unroll
            for (int hh = 0; hh < 2; hh++) {
                float bm = -1e30f;
#pragma unroll
                for (int nt = 0; nt < 8; nt++) {
                    bm = fmaxf(bm, sacc[mt][nt][2 * hh]);
                    bm = fmaxf(bm, sacc[mt][nt][2 * hh + 1]);
                }
                bm = fmaxf(bm, __shfl_xor_sync(0xffffffffu, bm, 1));
                bm = fmaxf(bm, __shfl_xor_sync(0xffffffffu, bm, 2));
                float mn = fmaxf(mrow[mt][hh], bm);
                float scale = __expf(mrow[mt][hh] - mn);
                mrow[mt][hh] = mn;
                lrow[mt][hh] *= scale;
#pragma unroll
                for (int nt = 0; nt < 8; nt++) {
                    oacc[mt][nt][2 * hh]     *= scale;
                    oacc[mt][nt][2 * hh + 1] *= scale;
                }
                float psum = 0.f;
                int row = mt * 16 + gid + hh * 8;
#pragma unroll
                for (int nt = 0; nt < 8; nt++) {
                    float p0 = __expf(sacc[mt][nt][2 * hh]     - mn);
                    float p1 = __expf(sacc[mt][nt][2 * hh + 1] - mn);
                    psum += p0 + p1;
                    *(bf162*)(Pw + row * AST + nt * 8 + 2 * tig) =
                        __floats2bfloat162_rn(p0, p1);
                }
                psum += __shfl_xor_sync(0xffffffffu, psum, 1);
                psum += __shfl_xor_sync(0xffffffffu, psum, 2);
                lrow[mt][hh] += psum;
            }
        __syncwarp();

        // ---- O += P @ V_jb (V via trans ldmatrix) ----
#pragma unroll
        for (int ks = 0; ks < 4; ks++) {
            uint32_t pf[2][4], vb4[4][4];
#pragma unroll
            for (int mt = 0; mt < 2; mt++)
                ldm_x4(pf[mt], PwB + (uint32_t)(((mt * 16 + (lane & 15)) * AST +
                         ks * 16 + (lane >> 4) * 8) * 2));
#pragma unroll
            for (int nb = 0; nb < 4; nb++)
                ldm_x4_t(vb4[nb], VbB + (uint32_t)(((jb * 64 + ks * 16 + vrow) * AST +
                           nb * 16 + vdim) * 2));
#pragma unroll
            for (int mt = 0; mt < 2; mt++)
#pragma unroll
                for (int nt = 0; nt < 8; nt++)
                    mma_bf16(oacc[mt][nt], pf[mt], &vb4[nt >> 1][(nt & 1) * 2]);
        }
    }

    // ---- epilogue: normalize, bf16 token-major out ----
    const int win = wh / 6, head = wh % 6;
#pragma unroll
    for (int mt = 0; mt < 2; mt++)
#pragma unroll
        for (int hh = 0; hh < 2; hh++) {
            float inv = 1.0f / lrow[mt][hh];
            int row = qr + mt * 16 + gid + hh * 8;
            bf16* op = out + ((size_t)win * 256 + row) * CDIM + head * 64;
#pragma unroll
            for (int nt = 0; nt < 8; nt++) {
                bf162 o = __floats2bfloat162_rn(
                    oacc[mt][nt][2 * hh] * inv,
                    oacc[mt][nt][2 * hh + 1] * inv);
                *(bf162*)(op + nt * 8 + 2 * tig) = o;
            }
        }
}

// ---------------------------------------------------------------------------
extern "C" void kernel_launch(void* const* d_in, const int* in_sizes, int n_in,
                              void* d_out, int out_size) {
    (void)in_sizes; (void)n_in; (void)out_size;
    const float* x   = (const float*)d_in[0];
    const float* Wq  = (const float*)d_in[1];
    const float* bq  = (const float*)d_in[2];
    const float* Wk  = (const float*)d_in[3];
    const float* bk  = (const float*)d_in[4];
    const float* Wv  = (const float*)d_in[5];
    const float* bv  = (const float*)d_in[6];
    const float* Wo  = (const float*)d_in[7];
    const float* bo  = (const float*)d_in[8];
    const float* g1  = (const float*)d_in[9];
    const float* be1 = (const float*)d_in[10];
    const float* g2  = (const float*)d_in[11];
    const float* be2 = (const float*)d_in[12];
    const float* W1  = (const float*)d_in[13];
    const float* B1  = (const float*)d_in[14];
    const float* W2  = (const float*)d_in[15];
    const float* B2  = (const float*)d_in[16];
    float* out = (float*)d_out;

    float *xw, *x2, *yb;
    bf16 *hb, *qb, *kb, *vb, *att, *mlp, *wt;
    cudaGetSymbolAddress((void**)&xw,  g_xw);
    cudaGetSymbolAddress((void**)&hb,  g_h);
    cudaGetSymbolAddress((void**)&qb,  g_q);
    cudaGetSymbolAddress((void**)&kb,  g_k);
    cudaGetSymbolAddress((void**)&vb,  g_v);
    cudaGetSymbolAddress((void**)&att, g_att);
    cudaGetSymbolAddress((void**)&x2,  g_x2);
    cudaGetSymbolAddress((void**)&mlp, g_mlp);
    cudaGetSymbolAddress((void**)&yb,  g_y);
    cudaGetSymbolAddress((void**)&wt,  g_wt);

    cudaFuncSetAttribute(attn_mma,
                         cudaFuncAttributeMaxDynamicSharedMemorySize, ATT_SMEM);

    // 0) weight transposes to K-major bf16
    transpose_kernel<<<dim3(12, 12), 256>>>(Wq, wt + 0,       CDIM, CDIM);
    transpose_kernel<<<dim3(12, 12), 256>>>(Wk, wt + 147456,  CDIM, CDIM);
    transpose_kernel<<<dim3(12, 12), 256>>>(Wv, wt + 294912,  CDIM, CDIM);
    transpose_kernel<<<dim3(12, 12), 256>>>(Wo, wt + 442368,  CDIM, CDIM);
    transpose_kernel<<<dim3(48, 12), 256>>>(W1, wt + 589824,  CDIM, MLPD);
    transpose_kernel<<<dim3(12, 48), 256>>>(W2, wt + 1179648, MLPD, CDIM);

    // 1) shift + window partition (fp32 residual stream)
    window_gather_kernel<<<dim3(12, 64, 16), 256>>>(x, xw);
    // 2) LN1 -> bf16
    ln_kernel<<<8192, 256>>>(xw, g1, be1, hb);
    // 3) QKV projections -> bf16 [win][head][t][64]
    mm_qkv<<<dim3(3, 512, 3), 256>>>(hb, wt, bq, bk, bv, qb, kb, vb);
    // 4) windowed attention (bf16 flash)
    attn_mma<<<1536, 256, ATT_SMEM>>>(qb, kb, vb, att);
    // 5) output projection + residual -> fp32
    mm_biasres<<<dim3(3, 512), 256>>>(att, wt + 442368, bo, xw, x2, CDIM);
    // 6) LN2 -> bf16
    ln_kernel<<<8192, 256>>>(x2, g2, be2, hb);
    // 7) MLP up + GELU -> bf16
    mm_gelu<<<dim3(12, 512), 256>>>(hb, wt + 589824, B1, mlp);
    // 8) MLP down + residual -> fp32
    mm_biasres<<<dim3(3, 512), 256>>>(mlp, wt + 1179648, B2, x2, yb, MLPD);
    // 9) reverse window partition + shift
    window_scatter_kernel<<<dim3(12, 64, 16), 256>>>(yb, out);
}

// round 11
// speedup vs baseline: 1.5198x; 1.0202x over previous
#include <cuda_runtime.h>
#include <cuda_bf16.h>
#include <math.h>
#include <stdint.h>

// ---------------------------------------------------------------------------
// SwinBlock3D: bf16 mma.sync GEMMs (2-stage static-smem core) + bf16 flash
// attention. LN1 fused with shift+window-gather; out-proj residual read
// straight from x (no xw intermediate). x(1,384,16,64,64) HEADS=6 MLP=1536
// ---------------------------------------------------------------------------

#define NTOK 65536
#define CDIM 384
#define MLPD 1536

typedef __nv_bfloat16 bf16;
typedef __nv_bfloat162 bf162;

__device__ bf16  g_h  [(size_t)NTOK * CDIM];
__device__ bf16  g_q  [(size_t)NTOK * CDIM];
__device__ bf16  g_k  [(size_t)NTOK * CDIM];
__device__ bf16  g_v  [(size_t)NTOK * CDIM];
__device__ bf16  g_att[(size_t)NTOK * CDIM];
__device__ float g_x2 [(size_t)NTOK * CDIM];
__device__ bf16  g_mlp[(size_t)NTOK * MLPD];
__device__ float g_y  [(size_t)NTOK * CDIM];
__device__ bf16  g_wt [1769472];

// ---------------- helpers ----------------------------------------------------
__device__ __forceinline__ uint32_t smem_u32(const void* p) {
    uint32_t a;
    asm("{ .reg .u64 t; cvta.to.shared.u64 t, %1; cvt.u32.u64 %0, t; }"
        : "=r"(a) : "l"(p));
    return a;
}
__device__ __forceinline__ void cp_async16(uint32_t s, const void* g) {
    asm volatile("cp.async.cg.shared.global [%0], [%1], 16;" :: "r"(s), "l"(g));
}
__device__ __forceinline__ void cp_commit() {
    asm volatile("cp.async.commit_group;");
}
template<int N> __device__ __forceinline__ void cp_wait() {
    asm volatile("cp.async.wait_group %0;" :: "n"(N));
}
__device__ __forceinline__ void ldm_x4(uint32_t r[4], uint32_t addr) {
    asm volatile("ldmatrix.sync.aligned.m8n8.x4.shared.b16 {%0,%1,%2,%3}, [%4];"
                 : "=r"(r[0]), "=r"(r[1]), "=r"(r[2]), "=r"(r[3]) : "r"(addr));
}
__device__ __forceinline__ void ldm_x4_t(uint32_t r[4], uint32_t addr) {
    asm volatile("ldmatrix.sync.aligned.m8n8.x4.trans.shared.b16 {%0,%1,%2,%3}, [%4];"
                 : "=r"(r[0]), "=r"(r[1]), "=r"(r[2]), "=r"(r[3]) : "r"(addr));
}
__device__ __forceinline__ void mma_bf16(float c[4], const uint32_t a[4],
                                         const uint32_t b[2]) {
    asm volatile(
        "mma.sync.aligned.m16n8k16.row.col.f32.bf16.bf16.f32 "
        "{%0,%1,%2,%3}, {%4,%5,%6,%7}, {%8,%9}, {%0,%1,%2,%3};"
        : "+f"(c[0]), "+f"(c[1]), "+f"(c[2]), "+f"(c[3])
        : "r"(a[0]), "r"(a[1]), "r"(a[2]), "r"(a[3]), "r"(b[0]), "r"(b[1]));
}
__device__ __forceinline__ uint2 pack4bf(float4 r) {
    bf162 lo = __floats2bfloat162_rn(r.x, r.y);
    bf162 hi = __floats2bfloat162_rn(r.z, r.w);
    uint2 u;
    u.x = *(uint32_t*)&lo;
    u.y = *(uint32_t*)&hi;
    return u;
}

extern __shared__ char s_dyn[];

__device__ __forceinline__ int token_index(int d, int h, int w) {
    int win = ((d >> 2) * 8 + (h >> 3)) * 8 + (w >> 3);
    int tok = ((d & 3) << 6) + ((h & 7) << 3) + (w & 7);
    return (win << 8) + tok;
}
// inverse: token n -> spatial offset in x (channel-major plane 65536)
__device__ __forceinline__ int token_spatial(int n) {
    int win = n >> 8, tok = n & 255;
    int d = ((win >> 6) << 2) | (tok >> 6);
    int h = (((win >> 3) & 7) << 3) | ((tok >> 3) & 7);
    int w = ((win & 7) << 3) | (tok & 7);
    int d0 = (d + 2) & 15, h0 = (h + 4) & 63, w0 = (w + 4) & 63;
    return d0 * 4096 + h0 * 64 + w0;
}

// ---------------- fused shift + window-gather + LN1 (x -> hb bf16) -----------
#define LN1_SMEM (384 * 33 * 4)

__global__ void ln1x_kernel(const float* __restrict__ x,
                            const float* __restrict__ gam,
                            const float* __restrict__ bet,
                            bf16* __restrict__ out) {
    float* sm = (float*)s_dyn;          // [384][33]
    const int wslab = blockIdx.x;       // 0..1 (32 w each)
    const int h0 = blockIdx.y;
    const int d0 = blockIdx.z;
    const int tid = threadIdx.x;
    const size_t base = (size_t)d0 * 4096 + h0 * 64 + wslab * 32;

    // load 384 channels x 32 w (float4-coalesced)
#pragma unroll
    for (int i = 0; i < 12; i++) {
        int idx = i * 256 + tid;        // 0..3071
        int ch = idx >> 3, f4 = (idx & 7) * 4;
        float4 v = *(const float4*)(x + (size_t)ch * 65536 + base + f4);
        float* d = sm + ch * 33 + f4;
        d[0] = v.x; d[1] = v.y; d[2] = v.z; d[3] = v.w;
    }
    __syncthreads();

    const int wi = tid >> 5, lane = tid & 31;
    const int d = (d0 + 14) & 15;
    const int h = (h0 + 60) & 63;
#pragma unroll
    for (int t = 0; t < 4; t++) {
        int wloc = wi + t * 8;          // 0..31
        float vals[12];
        float s = 0.f, ss = 0.f;
#pragma unroll
        for (int j = 0; j < 12; j++) {
            float v = sm[(lane + 32 * j) * 33 + wloc];
            vals[j] = v; s += v; ss += v * v;
        }
#pragma unroll
        for (int off = 16; off; off >>= 1) {
            s  += __shfl_xor_sync(0xffffffffu, s,  off);
            ss += __shfl_xor_sync(0xffffffffu, ss, off);
        }
        float mean = s * (1.0f / CDIM);
        float var  = ss * (1.0f / CDIM) - mean * mean;
        float rstd = rsqrtf(var + 1e-5f);
        int w = (wslab * 32 + wloc + 60) & 63;
        int n = token_index(d, h, w);
        bf16* op = out + (size_t)n * CDIM;
#pragma unroll
        for (int j = 0; j < 12; j++) {
            int ch = lane + 32 * j;
            float r = (vals[j] - mean) * rstd * gam[ch] + bet[ch];
            op[ch] = __float2bfloat16(r);
        }
    }
}

// ---------------- weight transposes ------------------------------------------
__global__ void transpose_kernel(const float* __restrict__ src,
                                 bf16* __restrict__ dst, int K, int N) {
    __shared__ float tile[32][33];
    int n0 = blockIdx.x * 32, k0 = blockIdx.y * 32;
    int tx = threadIdx.x & 31, ty = threadIdx.x >> 5;
#pragma unroll
    for (int i = ty; i < 32; i += 8)
        tile[i][tx] = src[(size_t)(k0 + i) * N + n0 + tx];
    __syncthreads();
#pragma unroll
    for (int i = ty; i < 32; i += 8)
        dst[(size_t)(n0 + i) * K + k0 + tx] = __float2bfloat16(tile[tx][i]);
}

// fused Q/K/V weight transpose (z selects source)
__global__ void transpose_qkv_kernel(const float* __restrict__ Wq,
                                     const float* __restrict__ Wk,
                                     const float* __restrict__ Wv,
                                     bf16* __restrict__ dst) {
    __shared__ float tile[32][33];
    const float* src = (blockIdx.z == 0) ? Wq : (blockIdx.z == 1) ? Wk : Wv;
    bf16* d = dst + (size_t)blockIdx.z * 147456;
    int n0 = blockIdx.x * 32, k0 = blockIdx.y * 32;
    int tx = threadIdx.x & 31, ty = threadIdx.x >> 5;
#pragma unroll
    for (int i = ty; i < 32; i += 8)
        tile[i][tx] = src[(size_t)(k0 + i) * CDIM + n0 + tx];
    __syncthreads();
#pragma unroll
    for (int i = ty; i < 32; i += 8)
        d[(size_t)(n0 + i) * CDIM + k0 + tx] = __float2bfloat16(tile[tx][i]);
}

// ---------------- reverse window partition + shift ---------------------------
__global__ void window_scatter_kernel(const float* __restrict__ y,
                                      float* __restrict__ out) {
    __shared__ float sm[32][65];
    const int c0 = blockIdx.x * 32;
    const int h0 = blockIdx.y;
    const int d0 = blockIdx.z;
    const int tid = threadIdx.x;
    {
        int w0 = tid >> 2;
        int cg = (tid & 3) * 8;
        int d = (d0 + 14) & 15;
        int h = (h0 + 60) & 63;
        int w = (w0 + 60) & 63;
        int n = token_index(d, h, w);
        const float* ip = y + (size_t)n * CDIM + c0 + cg;
        float4 a = *(const float4*)ip;
        float4 b = *(const float4*)(ip + 4);
        sm[cg + 0][w0] = a.x; sm[cg + 1][w0] = a.y;
        sm[cg + 2][w0] = a.z; sm[cg + 3][w0] = a.w;
        sm[cg + 4][w0] = b.x; sm[cg + 5][w0] = b.y;
        sm[cg + 6][w0] = b.z; sm[cg + 7][w0] = b.w;
    }
    __syncthreads();
    int cl = tid >> 4;
    int v4 = (tid & 15) * 4;
    float* op = out + (size_t)(c0 + cl) * 65536 + d0 * 4096 + h0 * 64 + v4;
    float4 o;
    o.x = sm[cl][v4 + 0]; o.y = sm[cl][v4 + 1];
    o.z = sm[cl][v4 + 2]; o.w = sm[cl][v4 + 3];
    *(float4*)op = o;
    float4 p;
    p.x = sm[cl + 16][v4 + 0]; p.y = sm[cl + 16][v4 + 1];
    p.z = sm[cl + 16][v4 + 2]; p.w = sm[cl + 16][v4 + 3];
    *(float4*)(op + (size_t)16 * 65536) = p;
}

// ---------------- layernorm 2 (fp32 token-major in, bf16 out) ----------------
__global__ void ln_kernel(const float* __restrict__ x,
                          const float* __restrict__ gam,
                          const float* __restrict__ bet,
                          bf16* __restrict__ out) {
    int warp = threadIdx.x >> 5;
    int lane = threadIdx.x & 31;
    size_t n = (size_t)blockIdx.x * 8 + warp;
    const float4* xr = (const float4*)(x + n * CDIM);
    float4 v[3];
    float s = 0.f, ss = 0.f;
#pragma unroll
    for (int i = 0; i < 3; i++) {
        v[i] = xr[i * 32 + lane];
        s += v[i].x + v[i].y + v[i].z + v[i].w;
        ss += v[i].x * v[i].x + v[i].y * v[i].y + v[i].z * v[i].z + v[i].w * v[i].w;
    }
#pragma unroll
    for (int off = 16; off; off >>= 1) {
        s  += __shfl_xor_sync(0xffffffffu, s,  off);
        ss += __shfl_xor_sync(0xffffffffu, ss, off);
    }
    float mean = s * (1.0f / CDIM);
    float var  = ss * (1.0f / CDIM) - mean * mean;
    float rstd = rsqrtf(var + 1e-5f);
    const float4* G = (const float4*)gam;
    const float4* B = (const float4*)bet;
    uint2* o = (uint2*)(out + n * CDIM);
#pragma unroll
    for (int i = 0; i < 3; i++) {
        float4 g = G[i * 32 + lane];
        float4 b = B[i * 32 + lane];
        float4 r;
        r.x = (v[i].x - mean) * rstd * g.x + b.x;
        r.y = (v[i].y - mean) * rstd * g.y + b.y;
        r.z = (v[i].z - mean) * rstd * g.z + b.z;
        r.w = (v[i].w - mean) * rstd * g.w + b.w;
        o[i * 32 + lane] = pack4bf(r);
    }
}

// ---------------- BF16 mma.sync GEMM core (2-stage, static smem) -------------
#define RS 24
#define KBLK 3072
#define BUFE 6144

__device__ __forceinline__ void mma_tile(const bf16* __restrict__ A,
                                         const bf16* __restrict__ Bt,
                                         int K, int rowBase, int colBase,
                                         float acc[4][4][4]) {
    __shared__ __align__(16) bf16 sA[2 * BUFE];
    __shared__ __align__(16) bf16 sB[2 * BUFE];
    const int tid = threadIdx.x;
    const int nk = K >> 5;
    const int wid = tid >> 5, lane = tid & 31;
    const int wr = (wid >> 2) * 64, wc = (wid & 3) * 32;
    const int arow = wr + (lane & 15);
    const int ahalf = (lane >> 4) * 8;
    const int brow = wc + (lane & 7) + ((lane >> 4) << 3);
    const int bhalf = ((lane >> 3) & 1) * 8;

#pragma unroll
    for (int mt = 0; mt < 4; mt++)
#pragma unroll
        for (int nt = 0; nt < 4; nt++)
#pragma unroll
            for (int f = 0; f < 4; f++) acc[mt][nt][f] = 0.f;

    auto stage = [&](int ks, int buf) {
        const bf16* Ap = A + (size_t)rowBase * K + ks * 32;
        const bf16* Bp = Bt + (size_t)colBase * K + ks * 32;
#pragma unroll
        for (int i = 0; i < 2; i++) {
            int c = tid * 2 + i;
            int r = c >> 2, piece = c & 3;
            int kb = piece >> 1, half = piece & 1;
            uint32_t dA = smem_u32(&sA[buf * BUFE + kb * KBLK + r * RS + half * 8]);
            uint32_t dB = smem_u32(&sB[buf * BUFE + kb * KBLK + r * RS + half * 8]);
            cp_async16(dA, Ap + (size_t)r * K + kb * 16 + half * 8);
            cp_async16(dB, Bp + (size_t)r * K + kb * 16 + half * 8);
        }
        cp_commit();
    };

    stage(0, 0);
    for (int k = 0; k < nk; k++) {
        int cur = k & 1;
        if (k + 1 < nk) { stage(k + 1, cur ^ 1); cp_wait<1>(); }
        else            { cp_wait<0>(); }
        __syncthreads();
        uint32_t aB = smem_u32(sA + cur * BUFE);
        uint32_t bB = smem_u32(sB + cur * BUFE);
#pragma unroll
        for (int kb = 0; kb < 2; kb++) {
            uint32_t af[4][4], bb[2][4];
#pragma unroll
            for (int mt = 0; mt < 4; mt++)
                ldm_x4(af[mt], aB + (uint32_t)((kb * KBLK +
                         (arow + mt * 16) * RS + ahalf) * 2));
#pragma unroll
            for (int nh = 0; nh < 2; nh++)
                ldm_x4(bb[nh], bB + (uint32_t)((kb * KBLK +
                         (brow + nh * 16) * RS + bhalf) * 2));
#pragma unroll
            for (int mt = 0; mt < 4; mt++)
#pragma unroll
                for (int nt = 0; nt < 4; nt++)
                    mma_bf16(acc[mt][nt], af[mt], &bb[nt >> 1][(nt & 1) * 2]);
        }
        __syncthreads();
    }
}

// ---- QKV GEMM: scatter bf16 to [win][head][t][64] ---------------------------
__global__ __launch_bounds__(256, 2)
void mm_qkv(const bf16* __restrict__ hb, const bf16* __restrict__ wt,
            const float* __restrict__ bq, const float* __restrict__ bk,
            const float* __restrict__ bv,
            bf16* __restrict__ q, bf16* __restrict__ k,
            bf16* __restrict__ v) {
    int g = blockIdx.z;
    const bf16* Bt = wt + (size_t)g * 147456;
    const float* bias = (g == 0) ? bq : (g == 1) ? bk : bv;
    bf16* out = (g == 0) ? q : (g == 1) ? k : v;
    int rowBase = blockIdx.y * 128, colBase = blockIdx.x * 128;

    float acc[4][4][4];
    mma_tile(hb, Bt, CDIM, rowBase, colBase, acc);

    const int lane = threadIdx.x & 31, wid = threadIdx.x >> 5;
    const int gid = lane >> 2, tig = lane & 3;
    const int wr = (wid >> 2) * 64, wc = (wid & 3) * 32;
#pragma unroll
    for (int mt = 0; mt < 4; mt++) {
        int r0 = rowBase + wr + mt * 16 + gid;
#pragma unroll
        for (int nt = 0; nt < 4; nt++) {
            int c = colBase + wc + nt * 8 + 2 * tig;
            int head = c >> 6, dd = c & 63;
            float bx = bias[c], by = bias[c + 1];
#pragma unroll
            for (int hh = 0; hh < 2; hh++) {
                int r = r0 + hh * 8;
                int win = r >> 8, t = r & 255;
                bf162 o = __floats2bfloat162_rn(acc[mt][nt][2 * hh] + bx,
                                                acc[mt][nt][2 * hh + 1] + by);
                *(bf162*)(out + (size_t)win * 98304 + head * 16384 +
                          t * 64 + dd) = o;
            }
        }
    }
}

// ---- out-proj GEMM + bias + residual read straight from x -------------------
__global__ __launch_bounds__(256, 2)
void mm_biasres_x(const bf16* __restrict__ A, const bf16* __restrict__ Bt,
                  const float* __restrict__ bias, const float* __restrict__ x,
                  float* __restrict__ out) {
    int rowBase = blockIdx.y * 128, colBase = blockIdx.x * 128;
    float acc[4][4][4];
    mma_tile(A, Bt, CDIM, rowBase, colBase, acc);

    const int lane = threadIdx.x & 31, wid = threadIdx.x >> 5;
    const int gid = lane >> 2, tig = lane & 3;
    const int wr = (wid >> 2) * 64, wc = (wid & 3) * 32;
#pragma unroll
    for (int mt = 0; mt < 4; mt++) {
        int r0 = rowBase + wr + mt * 16 + gid;
#pragma unroll
        for (int hh = 0; hh < 2; hh++) {
            int n = r0 + hh * 8;
            size_t sp = (size_t)token_spatial(n);
#pragma unroll
            for (int nt = 0; nt < 4; nt++) {
                int c = colBase + wc + nt * 8 + 2 * tig;
                float rx = x[(size_t)c * 65536 + sp];
                float ry = x[(size_t)(c + 1) * 65536 + sp];
                float2 o = make_float2(acc[mt][nt][2 * hh] + bias[c] + rx,
                                       acc[mt][nt][2 * hh + 1] + bias[c + 1] + ry);
                *(float2*)(out + (size_t)n * CDIM + c) = o;
            }
        }
    }
}

// ---- GEMM + bias + residual (token-major fp32 residual) ---------------------
__global__ __launch_bounds__(256, 2)
void mm_biasres(const bf16* __restrict__ A, const bf16* __restrict__ Bt,
                const float* __restrict__ bias, const float* __restrict__ res,
                float* __restrict__ out, int K) {
    int rowBase = blockIdx.y * 128, colBase = blockIdx.x * 128;
    float acc[4][4][4];
    mma_tile(A, Bt, K, rowBase, colBase, acc);

    const int lane = threadIdx.x & 31, wid = threadIdx.x >> 5;
    const int gid = lane >> 2, tig = lane & 3;
    const int wr = (wid >> 2) * 64, wc = (wid & 3) * 32;
#pragma unroll
    for (int mt = 0; mt < 4; mt++) {
        int r0 = rowBase + wr + mt * 16 + gid;
#pragma unroll
        for (int nt = 0; nt < 4; nt++) {
            int c = colBase + wc + nt * 8 + 2 * tig;
            float bx = bias[c], by = bias[c + 1];
#pragma unroll
            for (int hh = 0; hh < 2; hh++) {
                size_t off = (size_t)(r0 + hh * 8) * CDIM + c;
                float2 rr = *(const float2*)(res + off);
                float2 o = make_float2(acc[mt][nt][2 * hh] + bx + rr.x,
                                       acc[mt][nt][2 * hh + 1] + by + rr.y);
                *(float2*)(out + off) = o;
            }
        }
    }
}

// ---- GEMM + bias + exact GELU (bf16 out, N=1536) ----------------------------
__device__ __forceinline__ float gelu_f(float v) {
    return 0.5f * v * (1.0f + erff(v * 0.70710678118654752440f));
}

__global__ __launch_bounds__(256, 2)
void mm_gelu(const bf16* __restrict__ A, const bf16* __restrict__ Bt,
             const float* __restrict__ bias, bf16* __restrict__ out) {
    int rowBase = blockIdx.y * 128, colBase = blockIdx.x * 128;
    float acc[4][4][4];
    mma_tile(A, Bt, CDIM, rowBase, colBase, acc);

    const int lane = threadIdx.x & 31, wid = threadIdx.x >> 5;
    const int gid = lane >> 2, tig = lane & 3;
    const int wr = (wid >> 2) * 64, wc = (wid & 3) * 32;
#pragma unroll
    for (int mt = 0; mt < 4; mt++) {
        int r0 = rowBase + wr + mt * 16 + gid;
#pragma unroll
        for (int nt = 0; nt < 4; nt++) {
            int c = colBase + wc + nt * 8 + 2 * tig;
            float bx = bias[c], by = bias[c + 1];
#pragma unroll
            for (int hh = 0; hh < 2; hh++) {
                size_t off = (size_t)(r0 + hh * 8) * MLPD + c;
                bf162 o = __floats2bfloat162_rn(
                    gelu_f(acc[mt][nt][2 * hh] + bx),
                    gelu_f(acc[mt][nt][2 * hh + 1] + by));
                *(bf162*)(out + off) = o;
            }
        }
    }
}

// ---------------- attention: bf16 flash, one CTA per (window, head) ----------
#define AST 88
#define ATT_SMEM (3 * 256 * AST * 2)

__global__ __launch_bounds__(256, 1)
void attn_mma(const bf16* __restrict__ q, const bf16* __restrict__ k,
              const bf16* __restrict__ v, bf16* __restrict__ out) {
    bf16* Kb = (bf16*)s_dyn;
    bf16* Vb = Kb + 256 * AST;
    bf16* Pb = Vb + 256 * AST;
    const int wh = blockIdx.x;
    const size_t base = (size_t)wh * 16384;
    const int tid = threadIdx.x;
    const int wid = tid >> 5, lane = tid & 31;
    const int gid = lane >> 2, tig = lane & 3;
    const int qr = wid * 32;
    bf16* Pw = Pb + wid * 32 * AST;
    const uint32_t KbB = smem_u32(Kb), VbB = smem_u32(Vb);
    const uint32_t PwB = smem_u32(Pw), PbB = smem_u32(Pb);

    {
        const uint4* Kg = (const uint4*)(k + base + (size_t)tid * 64);
        const uint4* Vg = (const uint4*)(v + base + (size_t)tid * 64);
        const uint4* Qg = (const uint4*)(q + base + (size_t)tid * 64);
        uint4* Kd = (uint4*)(Kb + tid * AST);
        uint4* Vd = (uint4*)(Vb + tid * AST);
        uint4* Qd = (uint4*)(Pb + tid * AST);
        bf162 sc = __float2bfloat162_rn(0.125f);
#pragma unroll
        for (int i = 0; i < 8; i++) {
            Kd[i] = Kg[i];
            Vd[i] = Vg[i];
            uint4 t = Qg[i];
            bf162* tp = (bf162*)&t;
#pragma unroll
            for (int j = 0; j < 4; j++) tp[j] = __hmul2(tp[j], sc);
            Qd[i] = t;
        }
    }
    __syncthreads();

    uint32_t qf[2][4][4];
#pragma unroll
    for (int mt = 0; mt < 2; mt++)
#pragma unroll
        for (int ks = 0; ks < 4; ks++)
            ldm_x4(qf[mt][ks], PbB + (uint32_t)(((qr + mt * 16 + (lane & 15)) * AST +
                     ks * 16 + (lane >> 4) * 8) * 2));
    __syncthreads();

    float oacc[2][8][4];
#pragma unroll
    for (int mt = 0; mt < 2; mt++)
#pragma unroll
        for (int nt = 0; nt < 8; nt++)
#pragma unroll
            for (int f = 0; f < 4; f++) oacc[mt][nt][f] = 0.f;
    float mrow[2][2] = {{-1e30f, -1e30f}, {-1e30f, -1e30f}};
    float lrow[2][2] = {{0.f, 0.f}, {0.f, 0.f}};

    const int kbrow = (lane & 7) + ((lane >> 4) << 3);
    const int kbhalf = ((lane >> 3) & 1) * 8;
    const int vrow = (lane & 7) + (((lane >> 3) & 1) << 3);
    const int vdim = (lane >> 4) * 8;

    for (int jb = 0; jb < 4; jb++) {
        float sacc[2][8][4];
#pragma unroll
        for (int mt = 0; mt < 2; mt++)
#pragma unroll
            for (int nt = 0; nt < 8; nt++)
#pragma unroll
                for (int f = 0; f < 4; f++) sacc[mt][nt][f] = 0.f;
#pragma unroll
        for (int ks = 0; ks < 4; ks++) {
            uint32_t kb4[4][4];
#pragma unroll
            for (int np = 0; np < 4; np++)
                ldm_x4(kb4[np], KbB + (uint32_t)(((jb * 64 + np * 16 + kbrow) * AST +
                         ks * 16 + kbhalf) * 2));
#pragma unroll
            for (int mt = 0; mt < 2; mt++)
#pragma unroll
                for (int nt = 0; nt < 8; nt++)
                    mma_bf16(sacc[mt][nt], qf[mt][ks], &kb4[nt >> 1][(nt & 1) * 2]);
        }

        __syncwarp();
#pragma unroll
        for (int mt = 0; mt < 2; mt++)
#pragma unroll
            for (int hh = 0; hh < 2; hh++) {
                float bm = -1e30f;
#pragma unroll
                for (int nt = 0; nt < 8; nt++) {
                    bm = fmaxf(bm, sacc[mt][nt][2 * hh]);
                    bm = fmaxf(bm, sacc[mt][nt][2 * hh + 1]);
                }
                bm = fmaxf(bm, __shfl_xor_sync(0xffffffffu, bm, 1));
                bm = fmaxf(bm, __shfl_xor_sync(0xffffffffu, bm, 2));
                float mn = fmaxf(mrow[mt][hh], bm);
                float scale = __expf(mrow[mt][hh] - mn);
                mrow[mt][hh] = mn;
                lrow[mt][hh] *= scale;
#pragma unroll
                for (int nt = 0; nt < 8; nt++) {
                    oacc[mt][nt][2 * hh]     *= scale;
                    oacc[mt][nt][2 * hh + 1] *= scale;
                }
                float psum = 0.f;
                int row = mt * 16 + gid + hh * 8;
#pragma unroll
                for (int nt = 0; nt < 8; nt++) {
                    float p0 = __expf(sacc[mt][nt][2 * hh]     - mn);
                    float p1 = __expf(sacc[mt][nt][2 * hh + 1] - mn);
                    psum += p0 + p1;
                    *(bf162*)(Pw + row * AST + nt * 8 + 2 * tig) =
                        __floats2bfloat162_rn(p0, p1);
                }
                psum += __shfl_xor_sync(0xffffffffu, psum, 1);
                psum += __shfl_xor_sync(0xffffffffu, psum, 2);
                lrow[mt][hh] += psum;
            }
        __syncwarp();

#pragma unroll
        for (int ks = 0; ks < 4; ks++) {
            uint32_t pf[2][4], vb4[4][4];
#pragma unroll
            for (int mt = 0; mt < 2; mt++)
                ldm_x4(pf[mt], PwB + (uint32_t)(((mt * 16 + (lane & 15)) * AST +
                         ks * 16 + (lane >> 4) * 8) * 2));
#pragma unroll
            for (int nb = 0; nb < 4; nb++)
                ldm_x4_t(vb4[nb], VbB + (uint32_t)(((jb * 64 + ks * 16 + vrow) * AST +
                           nb * 16 + vdim) * 2));
#pragma unroll
            for (int mt = 0; mt < 2; mt++)
#pragma unroll
                for (int nt = 0; nt < 8; nt++)
                    mma_bf16(oacc[mt][nt], pf[mt], &vb4[nt >> 1][(nt & 1) * 2]);
        }
    }

    const int win = wh / 6, head = wh % 6;
#pragma unroll
    for (int mt = 0; mt < 2; mt++)
#pragma unroll
        for (int hh = 0; hh < 2; hh++) {
            float inv = 1.0f / lrow[mt][hh];
            int row = qr + mt * 16 + gid + hh * 8;
            bf16* op = out + ((size_t)win * 256 + row) * CDIM + head * 64;
#pragma unroll
            for (int nt = 0; nt < 8; nt++) {
                bf162 o = __floats2bfloat162_rn(
                    oacc[mt][nt][2 * hh] * inv,
                    oacc[mt][nt][2 * hh + 1] * inv);
                *(bf162*)(op + nt * 8 + 2 * tig) = o;
            }
        }
}

// ---------------------------------------------------------------------------
extern "C" void kernel_launch(void* const* d_in, const int* in_sizes, int n_in,
                              void* d_out, int out_size) {
    (void)in_sizes; (void)n_in; (void)out_size;
    const float* x   = (const float*)d_in[0];
    const float* Wq  = (const float*)d_in[1];
    const float* bq  = (const float*)d_in[2];
    const float* Wk  = (const float*)d_in[3];
    const float* bk  = (const float*)d_in[4];
    const float* Wv  = (const float*)d_in[5];
    const float* bv  = (const float*)d_in[6];
    const float* Wo  = (const float*)d_in[7];
    const float* bo  = (const float*)d_in[8];
    const float* g1  = (const float*)d_in[9];
    const float* be1 = (const float*)d_in[10];
    const float* g2  = (const float*)d_in[11];
    const float* be2 = (const float*)d_in[12];
    const float* W1  = (const float*)d_in[13];
    const float* B1  = (const float*)d_in[14];
    const float* W2  = (const float*)d_in[15];
    const float* B2  = (const float*)d_in[16];
    float* out = (float*)d_out;

    float *x2, *yb;
    bf16 *hb, *qb, *kb, *vb, *att, *mlp, *wt;
    cudaGetSymbolAddress((void**)&hb,  g_h);
    cudaGetSymbolAddress((void**)&qb,  g_q);
    cudaGetSymbolAddress((void**)&kb,  g_k);
    cudaGetSymbolAddress((void**)&vb,  g_v);
    cudaGetSymbolAddress((void**)&att, g_att);
    cudaGetSymbolAddress((void**)&x2,  g_x2);
    cudaGetSymbolAddress((void**)&mlp, g_mlp);
    cudaGetSymbolAddress((void**)&yb,  g_y);
    cudaGetSymbolAddress((void**)&wt,  g_wt);

    cudaFuncSetAttribute(ln1x_kernel,
                         cudaFuncAttributeMaxDynamicSharedMemorySize, LN1_SMEM);
    cudaFuncSetAttribute(attn_mma,
                         cudaFuncAttributeMaxDynamicSharedMemorySize, ATT_SMEM);

    // 1) fused shift + window-gather + LN1 -> hb bf16
    ln1x_kernel<<<dim3(2, 64, 16), 256, LN1_SMEM>>>(x, g1, be1, hb);
    // 2) QKV weight transpose (fused, z=3)
    transpose_qkv_kernel<<<dim3(12, 12, 3), 256>>>(Wq, Wk, Wv, wt);
    // 3) Wo transpose
    transpose_kernel<<<dim3(12, 12), 256>>>(Wo, wt + 442368, CDIM, CDIM);
    // 4) QKV projections  (profiled launch)
    mm_qkv<<<dim3(3, 512, 3), 256>>>(hb, wt, bq, bk, bv, qb, kb, vb);
    // 5-6) MLP weight transposes
    transpose_kernel<<<dim3(48, 12), 256>>>(W1, wt + 589824,  CDIM, MLPD);
    transpose_kernel<<<dim3(12, 48), 256>>>(W2, wt + 1179648, MLPD, CDIM);
    // 7) windowed attention (bf16 flash)
    attn_mma<<<1536, 256, ATT_SMEM>>>(qb, kb, vb, att);
    // 8) output projection + bias + residual-from-x -> x2 fp32
    mm_biasres_x<<<dim3(3, 512), 256>>>(att, wt + 442368, bo, x, x2);
    // 9) LN2 -> bf16
    ln_kernel<<<8192, 256>>>(x2, g2, be2, hb);
    // 10) MLP up + GELU -> bf16
    mm_gelu<<<dim3(12, 512), 256>>>(hb, wt + 589824, B1, mlp);
    // 11) MLP down + residual -> fp32
    mm_biasres<<<dim3(3, 512), 256>>>(mlp, wt + 1179648, B2, x2, yb, MLPD);
    // 12) reverse window partition + shift
    window_scatter_kernel<<<dim3(12, 64, 16), 256>>>(yb, out);
}

// round 12
// speedup vs baseline: 1.5615x; 1.0275x over previous
#include <cuda_runtime.h>
#include <cuda_bf16.h>
#include <math.h>
#include <stdint.h>

// ---------------------------------------------------------------------------
// SwinBlock3D: bf16 mma.sync GEMMs (3-stage cp.async pipeline, constant buffer
// rotation) + bf16 flash attention. LN1 fused with shift+gather; out-proj
// residual read from x. x(1,384,16,64,64) HEADS=6 MLP=1536
// ---------------------------------------------------------------------------

#define NTOK 65536
#define CDIM 384
#define MLPD 1536

typedef __nv_bfloat16 bf16;
typedef __nv_bfloat162 bf162;

__device__ bf16  g_h  [(size_t)NTOK * CDIM];
__device__ bf16  g_q  [(size_t)NTOK * CDIM];
__device__ bf16  g_k  [(size_t)NTOK * CDIM];
__device__ bf16  g_v  [(size_t)NTOK * CDIM];
__device__ bf16  g_att[(size_t)NTOK * CDIM];
__device__ float g_x2 [(size_t)NTOK * CDIM];
__device__ bf16  g_mlp[(size_t)NTOK * MLPD];
__device__ float g_y  [(size_t)NTOK * CDIM];
__device__ bf16  g_wt [1769472];

// ---------------- helpers ----------------------------------------------------
__device__ __forceinline__ uint32_t smem_u32(const void* p) {
    uint32_t a;
    asm("{ .reg .u64 t; cvta.to.shared.u64 t, %1; cvt.u32.u64 %0, t; }"
        : "=r"(a) : "l"(p));
    return a;
}
__device__ __forceinline__ void cp_async16(uint32_t s, const void* g) {
    asm volatile("cp.async.cg.shared.global [%0], [%1], 16;" :: "r"(s), "l"(g));
}
__device__ __forceinline__ void cp_commit() {
    asm volatile("cp.async.commit_group;");
}
template<int N> __device__ __forceinline__ void cp_wait() {
    asm volatile("cp.async.wait_group %0;" :: "n"(N));
}
__device__ __forceinline__ void ldm_x4(uint32_t r[4], uint32_t addr) {
    asm volatile("ldmatrix.sync.aligned.m8n8.x4.shared.b16 {%0,%1,%2,%3}, [%4];"
                 : "=r"(r[0]), "=r"(r[1]), "=r"(r[2]), "=r"(r[3]) : "r"(addr));
}
__device__ __forceinline__ void ldm_x4_t(uint32_t r[4], uint32_t addr) {
    asm volatile("ldmatrix.sync.aligned.m8n8.x4.trans.shared.b16 {%0,%1,%2,%3}, [%4];"
                 : "=r"(r[0]), "=r"(r[1]), "=r"(r[2]), "=r"(r[3]) : "r"(addr));
}
__device__ __forceinline__ void mma_bf16(float c[4], const uint32_t a[4],
                                         const uint32_t b[2]) {
    asm volatile(
        "mma.sync.aligned.m16n8k16.row.col.f32.bf16.bf16.f32 "
        "{%0,%1,%2,%3}, {%4,%5,%6,%7}, {%8,%9}, {%0,%1,%2,%3};"
        : "+f"(c[0]), "+f"(c[1]), "+f"(c[2]), "+f"(c[3])
        : "r"(a[0]), "r"(a[1]), "r"(a[2]), "r"(a[3]), "r"(b[0]), "r"(b[1]));
}
__device__ __forceinline__ uint2 pack4bf(float4 r) {
    bf162 lo = __floats2bfloat162_rn(r.x, r.y);
    bf162 hi = __floats2bfloat162_rn(r.z, r.w);
    uint2 u;
    u.x = *(uint32_t*)&lo;
    u.y = *(uint32_t*)&hi;
    return u;
}

extern __shared__ char s_dyn[];

__device__ __forceinline__ int token_index(int d, int h, int w) {
    int win = ((d >> 2) * 8 + (h >> 3)) * 8 + (w >> 3);
    int tok = ((d & 3) << 6) + ((h & 7) << 3) + (w & 7);
    return (win << 8) + tok;
}
__device__ __forceinline__ int token_spatial(int n) {
    int win = n >> 8, tok = n & 255;
    int d = ((win >> 6) << 2) | (tok >> 6);
    int h = (((win >> 3) & 7) << 3) | ((tok >> 3) & 7);
    int w = ((win & 7) << 3) | (tok & 7);
    int d0 = (d + 2) & 15, h0 = (h + 4) & 63, w0 = (w + 4) & 63;
    return d0 * 4096 + h0 * 64 + w0;
}

// ---------------- fused shift + window-gather + LN1 (x -> hb bf16) -----------
#define LN1_SMEM (384 * 33 * 4)

__global__ void ln1x_kernel(const float* __restrict__ x,
                            const float* __restrict__ gam,
                            const float* __restrict__ bet,
                            bf16* __restrict__ out) {
    float* sm = (float*)s_dyn;
    const int wslab = blockIdx.x;
    const int h0 = blockIdx.y;
    const int d0 = blockIdx.z;
    const int tid = threadIdx.x;
    const size_t base = (size_t)d0 * 4096 + h0 * 64 + wslab * 32;

#pragma unroll
    for (int i = 0; i < 12; i++) {
        int idx = i * 256 + tid;
        int ch = idx >> 3, f4 = (idx & 7) * 4;
        float4 v = *(const float4*)(x + (size_t)ch * 65536 + base + f4);
        float* d = sm + ch * 33 + f4;
        d[0] = v.x; d[1] = v.y; d[2] = v.z; d[3] = v.w;
    }
    __syncthreads();

    const int wi = tid >> 5, lane = tid & 31;
    const int d = (d0 + 14) & 15;
    const int h = (h0 + 60) & 63;
#pragma unroll
    for (int t = 0; t < 4; t++) {
        int wloc = wi + t * 8;
        float vals[12];
        float s = 0.f, ss = 0.f;
#pragma unroll
        for (int j = 0; j < 12; j++) {
            float v = sm[(lane + 32 * j) * 33 + wloc];
            vals[j] = v; s += v; ss += v * v;
        }
#pragma unroll
        for (int off = 16; off; off >>= 1) {
            s  += __shfl_xor_sync(0xffffffffu, s,  off);
            ss += __shfl_xor_sync(0xffffffffu, ss, off);
        }
        float mean = s * (1.0f / CDIM);
        float var  = ss * (1.0f / CDIM) - mean * mean;
        float rstd = rsqrtf(var + 1e-5f);
        int w = (wslab * 32 + wloc + 60) & 63;
        int n = token_index(d, h, w);
        bf16* op = out + (size_t)n * CDIM;
#pragma unroll
        for (int j = 0; j < 12; j++) {
            int ch = lane + 32 * j;
            float r = (vals[j] - mean) * rstd * gam[ch] + bet[ch];
            op[ch] = __float2bfloat16(r);
        }
    }
}

// ---------------- weight transposes ------------------------------------------
__global__ void transpose_kernel(const float* __restrict__ src,
                                 bf16* __restrict__ dst, int K, int N) {
    __shared__ float tile[32][33];
    int n0 = blockIdx.x * 32, k0 = blockIdx.y * 32;
    int tx = threadIdx.x & 31, ty = threadIdx.x >> 5;
#pragma unroll
    for (int i = ty; i < 32; i += 8)
        tile[i][tx] = src[(size_t)(k0 + i) * N + n0 + tx];
    __syncthreads();
#pragma unroll
    for (int i = ty; i < 32; i += 8)
        dst[(size_t)(n0 + i) * K + k0 + tx] = __float2bfloat16(tile[tx][i]);
}

__global__ void transpose_qkv_kernel(const float* __restrict__ Wq,
                                     const float* __restrict__ Wk,
                                     const float* __restrict__ Wv,
                                     bf16* __restrict__ dst) {
    __shared__ float tile[32][33];
    const float* src = (blockIdx.z == 0) ? Wq : (blockIdx.z == 1) ? Wk : Wv;
    bf16* d = dst + (size_t)blockIdx.z * 147456;
    int n0 = blockIdx.x * 32, k0 = blockIdx.y * 32;
    int tx = threadIdx.x & 31, ty = threadIdx.x >> 5;
#pragma unroll
    for (int i = ty; i < 32; i += 8)
        tile[i][tx] = src[(size_t)(k0 + i) * CDIM + n0 + tx];
    __syncthreads();
#pragma unroll
    for (int i = ty; i < 32; i += 8)
        d[(size_t)(n0 + i) * CDIM + k0 + tx] = __float2bfloat16(tile[tx][i]);
}

// ---------------- reverse window partition + shift ---------------------------
__global__ void window_scatter_kernel(const float* __restrict__ y,
                                      float* __restrict__ out) {
    __shared__ float sm[32][65];
    const int c0 = blockIdx.x * 32;
    const int h0 = blockIdx.y;
    const int d0 = blockIdx.z;
    const int tid = threadIdx.x;
    {
        int w0 = tid >> 2;
        int cg = (tid & 3) * 8;
        int d = (d0 + 14) & 15;
        int h = (h0 + 60) & 63;
        int w = (w0 + 60) & 63;
        int n = token_index(d, h, w);
        const float* ip = y + (size_t)n * CDIM + c0 + cg;
        float4 a = *(const float4*)ip;
        float4 b = *(const float4*)(ip + 4);
        sm[cg + 0][w0] = a.x; sm[cg + 1][w0] = a.y;
        sm[cg + 2][w0] = a.z; sm[cg + 3][w0] = a.w;
        sm[cg + 4][w0] = b.x; sm[cg + 5][w0] = b.y;
        sm[cg + 6][w0] = b.z; sm[cg + 7][w0] = b.w;
    }
    __syncthreads();
    int cl = tid >> 4;
    int v4 = (tid & 15) * 4;
    float* op = out + (size_t)(c0 + cl) * 65536 + d0 * 4096 + h0 * 64 + v4;
    float4 o;
    o.x = sm[cl][v4 + 0]; o.y = sm[cl][v4 + 1];
    o.z = sm[cl][v4 + 2]; o.w = sm[cl][v4 + 3];
    *(float4*)op = o;
    float4 p;
    p.x = sm[cl + 16][v4 + 0]; p.y = sm[cl + 16][v4 + 1];
    p.z = sm[cl + 16][v4 + 2]; p.w = sm[cl + 16][v4 + 3];
    *(float4*)(op + (size_t)16 * 65536) = p;
}

// ---------------- layernorm 2 ------------------------------------------------
__global__ void ln_kernel(const float* __restrict__ x,
                          const float* __restrict__ gam,
                          const float* __restrict__ bet,
                          bf16* __restrict__ out) {
    int warp = threadIdx.x >> 5;
    int lane = threadIdx.x & 31;
    size_t n = (size_t)blockIdx.x * 8 + warp;
    const float4* xr = (const float4*)(x + n * CDIM);
    float4 v[3];
    float s = 0.f, ss = 0.f;
#pragma unroll
    for (int i = 0; i < 3; i++) {
        v[i] = xr[i * 32 + lane];
        s += v[i].x + v[i].y + v[i].z + v[i].w;
        ss += v[i].x * v[i].x + v[i].y * v[i].y + v[i].z * v[i].z + v[i].w * v[i].w;
    }
#pragma unroll
    for (int off = 16; off; off >>= 1) {
        s  += __shfl_xor_sync(0xffffffffu, s,  off);
        ss += __shfl_xor_sync(0xffffffffu, ss, off);
    }
    float mean = s * (1.0f / CDIM);
    float var  = ss * (1.0f / CDIM) - mean * mean;
    float rstd = rsqrtf(var + 1e-5f);
    const float4* G = (const float4*)gam;
    const float4* B = (const float4*)bet;
    uint2* o = (uint2*)(out + n * CDIM);
#pragma unroll
    for (int i = 0; i < 3; i++) {
        float4 g = G[i * 32 + lane];
        float4 b = B[i * 32 + lane];
        float4 r;
        r.x = (v[i].x - mean) * rstd * g.x + b.x;
        r.y = (v[i].y - mean) * rstd * g.y + b.y;
        r.z = (v[i].z - mean) * rstd * g.z + b.z;
        r.w = (v[i].w - mean) * rstd * g.w + b.w;
        o[i * 32 + lane] = pack4bf(r);
    }
}

// ---------------- BF16 GEMM core: 3-stage pipeline, 1 sync/stage -------------
// Buffer rotation fully unrolled (nk % 3 == 0) so all buffer indices are
// compile-time; smem bases precomputed to avoid register-pressure spills.
#define RS 24
#define KBLK 3072
#define BUFE 6144
#define GSMEM (6 * BUFE * 2)   // 73728 B: sA[3 bufs] + sB[3 bufs]

__device__ __forceinline__ void mma_tile(const bf16* __restrict__ A,
                                         const bf16* __restrict__ Bt,
                                         int K, int rowBase, int colBase,
                                         float acc[4][4][4]) {
    bf16* sA = (bf16*)s_dyn;
    bf16* sB = sA + 3 * BUFE;
    const int tid = threadIdx.x;
    const int nk = K >> 5;                 // 12 or 48, divisible by 3
    const int wid = tid >> 5, lane = tid & 31;
    const int wr = (wid >> 2) * 64, wc = (wid & 3) * 32;
    const int arow = wr + (lane & 15);
    const int ahalf = (lane >> 4) * 8;
    const int brow = wc + (lane & 7) + ((lane >> 4) << 3);
    const int bhalf = ((lane >> 3) & 1) * 8;

    // per-thread staging offsets: r = tid>>1, kb = tid&1, two halves
    const int r_st = tid >> 1, kb_st = tid & 1;
    const uint32_t soff = (uint32_t)((kb_st * KBLK + r_st * RS) * 2);
    const size_t goff = (size_t)r_st * K + kb_st * 16;
    uint32_t aBase[3], bBase[3];
#pragma unroll
    for (int i = 0; i < 3; i++) {
        aBase[i] = smem_u32(sA + i * BUFE) + soff;
        bBase[i] = smem_u32(sB + i * BUFE) + soff;
    }
    const bf16* Ag = A + (size_t)rowBase * K + goff;
    const bf16* Bg = Bt + (size_t)colBase * K + goff;

#pragma unroll
    for (int mt = 0; mt < 4; mt++)
#pragma unroll
        for (int nt = 0; nt < 4; nt++)
#pragma unroll
            for (int f = 0; f < 4; f++) acc[mt][nt][f] = 0.f;

    auto stage = [&](int ks, uint32_t aD, uint32_t bD) {
        const bf16* Ap = Ag + ks * 32;
        const bf16* Bp = Bg + ks * 32;
        cp_async16(aD,      Ap);
        cp_async16(aD + 16, Ap + 8);
        cp_async16(bD,      Bp);
        cp_async16(bD + 16, Bp + 8);
        cp_commit();
    };

    stage(0, aBase[0], bBase[0]);
    stage(1, aBase[1], bBase[1]);

    for (int k = 0; k < nk; k += 3) {
#pragma unroll
        for (int j = 0; j < 3; j++) {
            const int kk = k + j;
            const int pb = (j + 2) % 3;      // compile-time per unrolled j
            if (kk == nk - 1) cp_wait<0>(); else cp_wait<1>();
            __syncthreads();
            if (kk + 2 < nk) stage(kk + 2, aBase[pb], bBase[pb]);
            uint32_t aB = aBase[j] - soff;
            uint32_t bB = bBase[j] - soff;
#pragma unroll
            for (int kb = 0; kb < 2; kb++) {
                uint32_t af[4][4], bb[2][4];
#pragma unroll
                for (int mt = 0; mt < 4; mt++)
                    ldm_x4(af[mt], aB + (uint32_t)((kb * KBLK +
                             (arow + mt * 16) * RS + ahalf) * 2));
#pragma unroll
                for (int nh = 0; nh < 2; nh++)
                    ldm_x4(bb[nh], bB + (uint32_t)((kb * KBLK +
                             (brow + nh * 16) * RS + bhalf) * 2));
#pragma unroll
                for (int mt = 0; mt < 4; mt++)
#pragma unroll
                    for (int nt = 0; nt < 4; nt++)
                        mma_bf16(acc[mt][nt], af[mt], &bb[nt >> 1][(nt & 1) * 2]);
            }
        }
    }
}

// ---- QKV GEMM: scatter bf16 to [win][head][t][64] ---------------------------
__global__ __launch_bounds__(256, 2)
void mm_qkv(const bf16* __restrict__ hb, const bf16* __restrict__ wt,
            const float* __restrict__ bq, const float* __restrict__ bk,
            const float* __restrict__ bv,
            bf16* __restrict__ q, bf16* __restrict__ k,
            bf16* __restrict__ v) {
    int g = blockIdx.z;
    const bf16* Bt = wt + (size_t)g * 147456;
    const float* bias = (g == 0) ? bq : (g == 1) ? bk : bv;
    bf16* out = (g == 0) ? q : (g == 1) ? k : v;
    int rowBase = blockIdx.y * 128, colBase = blockIdx.x * 128;

    float acc[4][4][4];
    mma_tile(hb, Bt, CDIM, rowBase, colBase, acc);

    const int lane = threadIdx.x & 31, wid = threadIdx.x >> 5;
    const int gid = lane >> 2, tig = lane & 3;
    const int wr = (wid >> 2) * 64, wc = (wid & 3) * 32;
#pragma unroll
    for (int mt = 0; mt < 4; mt++) {
        int r0 = rowBase + wr + mt * 16 + gid;
#pragma unroll
        for (int nt = 0; nt < 4; nt++) {
            int c = colBase + wc + nt * 8 + 2 * tig;
            int head = c >> 6, dd = c & 63;
            float bx = bias[c], by = bias[c + 1];
#pragma unroll
            for (int hh = 0; hh < 2; hh++) {
                int r = r0 + hh * 8;
                int win = r >> 8, t = r & 255;
                bf162 o = __floats2bfloat162_rn(acc[mt][nt][2 * hh] + bx,
                                                acc[mt][nt][2 * hh + 1] + by);
                *(bf162*)(out + (size_t)win * 98304 + head * 16384 +
                          t * 64 + dd) = o;
            }
        }
    }
}

// ---- out-proj GEMM + bias + residual read straight from x -------------------
__global__ __launch_bounds__(256, 2)
void mm_biasres_x(const bf16* __restrict__ A, const bf16* __restrict__ Bt,
                  const float* __restrict__ bias, const float* __restrict__ x,
                  float* __restrict__ out) {
    int rowBase = blockIdx.y * 128, colBase = blockIdx.x * 128;
    float acc[4][4][4];
    mma_tile(A, Bt, CDIM, rowBase, colBase, acc);

    const int lane = threadIdx.x & 31, wid = threadIdx.x >> 5;
    const int gid = lane >> 2, tig = lane & 3;
    const int wr = (wid >> 2) * 64, wc = (wid & 3) * 32;
#pragma unroll
    for (int mt = 0; mt < 4; mt++) {
        int r0 = rowBase + wr + mt * 16 + gid;
#pragma unroll
        for (int hh = 0; hh < 2; hh++) {
            int n = r0 + hh * 8;
            size_t sp = (size_t)token_spatial(n);
#pragma unroll
            for (int nt = 0; nt < 4; nt++) {
                int c = colBase + wc + nt * 8 + 2 * tig;
                float rx = x[(size_t)c * 65536 + sp];
                float ry = x[(size_t)(c + 1) * 65536 + sp];
                float2 o = make_float2(acc[mt][nt][2 * hh] + bias[c] + rx,
                                       acc[mt][nt][2 * hh + 1] + bias[c + 1] + ry);
                *(float2*)(out + (size_t)n * CDIM + c) = o;
            }
        }
    }
}

// ---- GEMM + bias + residual (token-major fp32 residual) ---------------------
__global__ __launch_bounds__(256, 2)
void mm_biasres(const bf16* __restrict__ A, const bf16* __restrict__ Bt,
                const float* __restrict__ bias, const float* __restrict__ res,
                float* __restrict__ out, int K) {
    int rowBase = blockIdx.y * 128, colBase = blockIdx.x * 128;
    float acc[4][4][4];
    mma_tile(A, Bt, K, rowBase, colBase, acc);

    const int lane = threadIdx.x & 31, wid = threadIdx.x >> 5;
    const int gid = lane >> 2, tig = lane & 3;
    const int wr = (wid >> 2) * 64, wc = (wid & 3) * 32;
#pragma unroll
    for (int mt = 0; mt < 4; mt++) {
        int r0 = rowBase + wr + mt * 16 + gid;
#pragma unroll
        for (int nt = 0; nt < 4; nt++) {
            int c = colBase + wc + nt * 8 + 2 * tig;
            float bx = bias[c], by = bias[c + 1];
#pragma unroll
            for (int hh = 0; hh < 2; hh++) {
                size_t off = (size_t)(r0 + hh * 8) * CDIM + c;
                float2 rr = *(const float2*)(res + off);
                float2 o = make_float2(acc[mt][nt][2 * hh] + bx + rr.x,
                                       acc[mt][nt][2 * hh + 1] + by + rr.y);
                *(float2*)(out + off) = o;
            }
        }
    }
}

// ---- GEMM + bias + exact GELU (bf16 out, N=1536) ----------------------------
__device__ __forceinline__ float gelu_f(float v) {
    return 0.5f * v * (1.0f + erff(v * 0.70710678118654752440f));
}

__global__ __launch_bounds__(256, 2)
void mm_gelu(const bf16* __restrict__ A, const bf16* __restrict__ Bt,
             const float* __restrict__ bias, bf16* __restrict__ out) {
    int rowBase = blockIdx.y * 128, colBase = blockIdx.x * 128;
    float acc[4][4][4];
    mma_tile(A, Bt, CDIM, rowBase, colBase, acc);

    const int lane = threadIdx.x & 31, wid = threadIdx.x >> 5;
    const int gid = lane >> 2, tig = lane & 3;
    const int wr = (wid >> 2) * 64, wc = (wid & 3) * 32;
#pragma unroll
    for (int mt = 0; mt < 4; mt++) {
        int r0 = rowBase + wr + mt * 16 + gid;
#pragma unroll
        for (int nt = 0; nt < 4; nt++) {
            int c = colBase + wc + nt * 8 + 2 * tig;
            float bx = bias[c], by = bias[c + 1];
#pragma unroll
            for (int hh = 0; hh < 2; hh++) {
                size_t off = (size_t)(r0 + hh * 8) * MLPD + c;
                bf162 o = __floats2bfloat162_rn(
                    gelu_f(acc[mt][nt][2 * hh] + bx),
                    gelu_f(acc[mt][nt][2 * hh + 1] + by));
                *(bf162*)(out + off) = o;
            }
        }
    }
}

// ---------------- attention: bf16 flash, one CTA per (window, head) ----------
#define AST 88
#define ATT_SMEM (3 * 256 * AST * 2)

__global__ __launch_bounds__(256, 1)
void attn_mma(const bf16* __restrict__ q, const bf16* __restrict__ k,
              const bf16* __restrict__ v, bf16* __restrict__ out) {
    bf16* Kb = (bf16*)s_dyn;
    bf16* Vb = Kb + 256 * AST;
    bf16* Pb = Vb + 256 * AST;
    const int wh = blockIdx.x;
    const size_t base = (size_t)wh * 16384;
    const int tid = threadIdx.x;
    const int wid = tid >> 5, lane = tid & 31;
    const int gid = lane >> 2, tig = lane & 3;
    const int qr = wid * 32;
    bf16* Pw = Pb + wid * 32 * AST;
    const uint32_t KbB = smem_u32(Kb), VbB = smem_u32(Vb);
    const uint32_t PwB = smem_u32(Pw), PbB = smem_u32(Pb);

    {
        const uint4* Kg = (const uint4*)(k + base + (size_t)tid * 64);
        const uint4* Vg = (const uint4*)(v + base + (size_t)tid * 64);
        const uint4* Qg = (const uint4*)(q + base + (size_t)tid * 64);
        uint4* Kd = (uint4*)(Kb + tid * AST);
        uint4* Vd = (uint4*)(Vb + tid * AST);
        uint4* Qd = (uint4*)(Pb + tid * AST);
        bf162 sc = __float2bfloat162_rn(0.125f);
#pragma unroll
        for (int i = 0; i < 8; i++) {
            Kd[i] = Kg[i];
            Vd[i] = Vg[i];
            uint4 t = Qg[i];
            bf162* tp = (bf162*)&t;
#pragma unroll
            for (int j = 0; j < 4; j++) tp[j] = __hmul2(tp[j], sc);
            Qd[i] = t;
        }
    }
    __syncthreads();

    uint32_t qf[2][4][4];
#pragma unroll
    for (int mt = 0; mt < 2; mt++)
#pragma unroll
        for (int ks = 0; ks < 4; ks++)
            ldm_x4(qf[mt][ks], PbB + (uint32_t)(((qr + mt * 16 + (lane & 15)) * AST +
                     ks * 16 + (lane >> 4) * 8) * 2));
    __syncthreads();

    float oacc[2][8][4];
#pragma unroll
    for (int mt = 0; mt < 2; mt++)
#pragma unroll
        for (int nt = 0; nt < 8; nt++)
#pragma unroll
            for (int f = 0; f < 4; f++) oacc[mt][nt][f] = 0.f;
    float mrow[2][2] = {{-1e30f, -1e30f}, {-1e30f, -1e30f}};
    float lrow[2][2] = {{0.f, 0.f}, {0.f, 0.f}};

    const int kbrow = (lane & 7) + ((lane >> 4) << 3);
    const int kbhalf = ((lane >> 3) & 1) * 8;
    const int vrow = (lane & 7) + (((lane >> 3) & 1) << 3);
    const int vdim = (lane >> 4) * 8;

    for (int jb = 0; jb < 4; jb++) {
        float sacc[2][8][4];
#pragma unroll
        for (int mt = 0; mt < 2; mt++)
#pragma unroll
            for (int nt = 0; nt < 8; nt++)
#pragma unroll
                for (int f = 0; f < 4; f++) sacc[mt][nt][f] = 0.f;
#pragma unroll
        for (int ks = 0; ks < 4; ks++) {
            uint32_t kb4[4][4];
#pragma unroll
            for (int np = 0; np < 4; np++)
                ldm_x4(kb4[np], KbB + (uint32_t)(((jb * 64 + np * 16 + kbrow) * AST +
                         ks * 16 + kbhalf) * 2));
#pragma unroll
            for (int mt = 0; mt < 2; mt++)
#pragma unroll
                for (int nt = 0; nt < 8; nt++)
                    mma_bf16(sacc[mt][nt], qf[mt][ks], &kb4[nt >> 1][(nt & 1) * 2]);
        }

        __syncwarp();
#pragma unroll
        for (int mt = 0; mt < 2; mt++)
#pragma unroll
            for (int hh = 0; hh < 2; hh++) {
                float bm = -1e30f;
#pragma unroll
                for (int nt = 0; nt < 8; nt++) {
                    bm = fmaxf(bm, sacc[mt][nt][2 * hh]);
                    bm = fmaxf(bm, sacc[mt][nt][2 * hh + 1]);
                }
                bm = fmaxf(bm, __shfl_xor_sync(0xffffffffu, bm, 1));
                bm = fmaxf(bm, __shfl_xor_sync(0xffffffffu, bm, 2));
                float mn = fmaxf(mrow[mt][hh], bm);
                float scale = __expf(mrow[mt][hh] - mn);
                mrow[mt][hh] = mn;
                lrow[mt][hh] *= scale;
#pragma unroll
                for (int nt = 0; nt < 8; nt++) {
                    oacc[mt][nt][2 * hh]     *= scale;
                    oacc[mt][nt][2 * hh + 1] *= scale;
                }
                float psum = 0.f;
                int row = mt * 16 + gid + hh * 8;
#pragma unroll
                for (int nt = 0; nt < 8; nt++) {
                    float p0 = __expf(sacc[mt][nt][2 * hh]     - mn);
                    float p1 = __expf(sacc[mt][nt][2 * hh + 1] - mn);
                    psum += p0 + p1;
                    *(bf162*)(Pw + row * AST + nt * 8 + 2 * tig) =
                        __floats2bfloat162_rn(p0, p1);
                }
                psum += __shfl_xor_sync(0xffffffffu, psum, 1);
                psum += __shfl_xor_sync(0xffffffffu, psum, 2);
                lrow[mt][hh] += psum;
            }
        __syncwarp();

#pragma unroll
        for (int ks = 0; ks < 4; ks++) {
            uint32_t pf[2][4], vb4[4][4];
#pragma unroll
            for (int mt = 0; mt < 2; mt++)
                ldm_x4(pf[mt], PwB + (uint32_t)(((mt * 16 + (lane & 15)) * AST +
                         ks * 16 + (lane >> 4) * 8) * 2));
#pragma unroll
            for (int nb = 0; nb < 4; nb++)
                ldm_x4_t(vb4[nb], VbB + (uint32_t)(((jb * 64 + ks * 16 + vrow) * AST +
                           nb * 16 + vdim) * 2));
#pragma unroll
            for (int mt = 0; mt < 2; mt++)
#pragma unroll
                for (int nt = 0; nt < 8; nt++)
                    mma_bf16(oacc[mt][nt], pf[mt], &vb4[nt >> 1][(nt & 1) * 2]);
        }
    }

    const int win = wh / 6, head = wh % 6;
#pragma unroll
    for (int mt = 0; mt < 2; mt++)
#pragma unroll
        for (int hh = 0; hh < 2; hh++) {
            float inv = 1.0f / lrow[mt][hh];
            int row = qr + mt * 16 + gid + hh * 8;
            bf16* op = out + ((size_t)win * 256 + row) * CDIM + head * 64;
#pragma unroll
            for (int nt = 0; nt < 8; nt++) {
                bf162 o = __floats2bfloat162_rn(
                    oacc[mt][nt][2 * hh] * inv,
                    oacc[mt][nt][2 * hh + 1] * inv);
                *(bf162*)(op + nt * 8 + 2 * tig) = o;
            }
        }
}

// ---------------------------------------------------------------------------
extern "C" void kernel_launch(void* const* d_in, const int* in_sizes, int n_in,
                              void* d_out, int out_size) {
    (void)in_sizes; (void)n_in; (void)out_size;
    const float* x   = (const float*)d_in[0];
    const float* Wq  = (const float*)d_in[1];
    const float* bq  = (const float*)d_in[2];
    const float* Wk  = (const float*)d_in[3];
    const float* bk  = (const float*)d_in[4];
    const float* Wv  = (const float*)d_in[5];
    const float* bv  = (const float*)d_in[6];
    const float* Wo  = (const float*)d_in[7];
    const float* bo  = (const float*)d_in[8];
    const float* g1  = (const float*)d_in[9];
    const float* be1 = (const float*)d_in[10];
    const float* g2  = (const float*)d_in[11];
    const float* be2 = (const float*)d_in[12];
    const float* W1  = (const float*)d_in[13];
    const float* B1  = (const float*)d_in[14];
    const float* W2  = (const float*)d_in[15];
    const float* B2  = (const float*)d_in[16];
    float* out = (float*)d_out;

    float *x2, *yb;
    bf16 *hb, *qb, *kb, *vb, *att, *mlp, *wt;
    cudaGetSymbolAddress((void**)&hb,  g_h);
    cudaGetSymbolAddress((void**)&qb,  g_q);
    cudaGetSymbolAddress((void**)&kb,  g_k);
    cudaGetSymbolAddress((void**)&vb,  g_v);
    cudaGetSymbolAddress((void**)&att, g_att);
    cudaGetSymbolAddress((void**)&x2,  g_x2);
    cudaGetSymbolAddress((void**)&mlp, g_mlp);
    cudaGetSymbolAddress((void**)&yb,  g_y);
    cudaGetSymbolAddress((void**)&wt,  g_wt);

    cudaFuncSetAttribute(ln1x_kernel,
                         cudaFuncAttributeMaxDynamicSharedMemorySize, LN1_SMEM);
    cudaFuncSetAttribute(attn_mma,
                         cudaFuncAttributeMaxDynamicSharedMemorySize, ATT_SMEM);
    cudaFuncSetAttribute(mm_qkv,
                         cudaFuncAttributeMaxDynamicSharedMemorySize, GSMEM);
    cudaFuncSetAttribute(mm_biasres_x,
                         cudaFuncAttributeMaxDynamicSharedMemorySize, GSMEM);
    cudaFuncSetAttribute(mm_biasres,
                         cudaFuncAttributeMaxDynamicSharedMemorySize, GSMEM);
    cudaFuncSetAttribute(mm_gelu,
                         cudaFuncAttributeMaxDynamicSharedMemorySize, GSMEM);

    // 1) fused shift + window-gather + LN1 -> hb bf16
    ln1x_kernel<<<dim3(2, 64, 16), 256, LN1_SMEM>>>(x, g1, be1, hb);
    // 2) QKV weight transpose
    transpose_qkv_kernel<<<dim3(12, 12, 3), 256>>>(Wq, Wk, Wv, wt);
    // 3) Wo transpose
    transpose_kernel<<<dim3(12, 12), 256>>>(Wo, wt + 442368, CDIM, CDIM);
    // 4) QKV projections (profiled launch)
    mm_qkv<<<dim3(3, 512, 3), 256, GSMEM>>>(hb, wt, bq, bk, bv, qb, kb, vb);
    // 5-6) MLP weight transposes
    transpose_kernel<<<dim3(48, 12), 256>>>(W1, wt + 589824,  CDIM, MLPD);
    transpose_kernel<<<dim3(12, 48), 256>>>(W2, wt + 1179648, MLPD, CDIM);
    // 7) windowed attention (bf16 flash)
    attn_mma<<<1536, 256, ATT_SMEM>>>(qb, kb, vb, att);
    // 8) output projection + bias + residual-from-x -> x2 fp32
    mm_biasres_x<<<dim3(3, 512), 256, GSMEM>>>(att, wt + 442368, bo, x, x2);
    // 9) LN2 -> bf16
    ln_kernel<<<8192, 256>>>(x2, g2, be2, hb);
    // 10) MLP up + GELU -> bf16
    mm_gelu<<<dim3(12, 512), 256, GSMEM>>>(hb, wt + 589824, B1, mlp);
    // 11) MLP down + residual -> fp32
    mm_biasres<<<dim3(3, 512), 256, GSMEM>>>(mlp, wt + 1179648, B2, x2, yb, MLPD);
    // 12) reverse window partition + shift
    window_scatter_kernel<<<dim3(12, 64, 16), 256>>>(yb, out);
}

// round 13
// speedup vs baseline: 2.2568x; 1.4453x over previous
#include <cuda_runtime.h>
#include <cuda_bf16.h>
#include <math.h>
#include <stdint.h>

// ---------------------------------------------------------------------------
// SwinBlock3D: bf16 mma.sync GEMMs (k64 stages, XOR-swizzled smem, 3-buffer
// cp.async pipeline) + bf16 flash attention. LN1 fused with shift+gather;
// out-proj residual from x. x(1,384,16,64,64) HEADS=6 MLP=1536
// ---------------------------------------------------------------------------

#define NTOK 65536
#define CDIM 384
#define MLPD 1536

typedef __nv_bfloat16 bf16;
typedef __nv_bfloat162 bf162;

__device__ bf16  g_h  [(size_t)NTOK * CDIM];
__device__ bf16  g_q  [(size_t)NTOK * CDIM];
__device__ bf16  g_k  [(size_t)NTOK * CDIM];
__device__ bf16  g_v  [(size_t)NTOK * CDIM];
__device__ bf16  g_att[(size_t)NTOK * CDIM];
__device__ float g_x2 [(size_t)NTOK * CDIM];
__device__ bf16  g_mlp[(size_t)NTOK * MLPD];
__device__ float g_y  [(size_t)NTOK * CDIM];
__device__ bf16  g_wt [1769472];

// ---------------- helpers ----------------------------------------------------
__device__ __forceinline__ uint32_t smem_u32(const void* p) {
    uint32_t a;
    asm("{ .reg .u64 t; cvta.to.shared.u64 t, %1; cvt.u32.u64 %0, t; }"
        : "=r"(a) : "l"(p));
    return a;
}
__device__ __forceinline__ void cp_async16(uint32_t s, const void* g) {
    asm volatile("cp.async.cg.shared.global [%0], [%1], 16;" :: "r"(s), "l"(g));
}
__device__ __forceinline__ void cp_commit() {
    asm volatile("cp.async.commit_group;");
}
template<int N> __device__ __forceinline__ void cp_wait() {
    asm volatile("cp.async.wait_group %0;" :: "n"(N));
}
__device__ __forceinline__ void ldm_x4(uint32_t r[4], uint32_t addr) {
    asm volatile("ldmatrix.sync.aligned.m8n8.x4.shared.b16 {%0,%1,%2,%3}, [%4];"
                 : "=r"(r[0]), "=r"(r[1]), "=r"(r[2]), "=r"(r[3]) : "r"(addr));
}
__device__ __forceinline__ void ldm_x4_t(uint32_t r[4], uint32_t addr) {
    asm volatile("ldmatrix.sync.aligned.m8n8.x4.trans.shared.b16 {%0,%1,%2,%3}, [%4];"
                 : "=r"(r[0]), "=r"(r[1]), "=r"(r[2]), "=r"(r[3]) : "r"(addr));
}
__device__ __forceinline__ void mma_bf16(float c[4], const uint32_t a[4],
                                         const uint32_t b[2]) {
    asm volatile(
        "mma.sync.aligned.m16n8k16.row.col.f32.bf16.bf16.f32 "
        "{%0,%1,%2,%3}, {%4,%5,%6,%7}, {%8,%9}, {%0,%1,%2,%3};"
        : "+f"(c[0]), "+f"(c[1]), "+f"(c[2]), "+f"(c[3])
        : "r"(a[0]), "r"(a[1]), "r"(a[2]), "r"(a[3]), "r"(b[0]), "r"(b[1]));
}
__device__ __forceinline__ uint2 pack4bf(float4 r) {
    bf162 lo = __floats2bfloat162_rn(r.x, r.y);
    bf162 hi = __floats2bfloat162_rn(r.z, r.w);
    uint2 u;
    u.x = *(uint32_t*)&lo;
    u.y = *(uint32_t*)&hi;
    return u;
}

extern __shared__ char s_dyn[];

__device__ __forceinline__ int token_index(int d, int h, int w) {
    int win = ((d >> 2) * 8 + (h >> 3)) * 8 + (w >> 3);
    int tok = ((d & 3) << 6) + ((h & 7) << 3) + (w & 7);
    return (win << 8) + tok;
}
__device__ __forceinline__ int token_spatial(int n) {
    int win = n >> 8, tok = n & 255;
    int d = ((win >> 6) << 2) | (tok >> 6);
    int h = (((win >> 3) & 7) << 3) | ((tok >> 3) & 7);
    int w = ((win & 7) << 3) | (tok & 7);
    int d0 = (d + 2) & 15, h0 = (h + 4) & 63, w0 = (w + 4) & 63;
    return d0 * 4096 + h0 * 64 + w0;
}

// ---------------- fused shift + window-gather + LN1 (x -> hb bf16) -----------
#define LN1_SMEM (384 * 33 * 4)

__global__ void ln1x_kernel(const float* __restrict__ x,
                            const float* __restrict__ gam,
                            const float* __restrict__ bet,
                            bf16* __restrict__ out) {
    float* sm = (float*)s_dyn;
    const int wslab = blockIdx.x;
    const int h0 = blockIdx.y;
    const int d0 = blockIdx.z;
    const int tid = threadIdx.x;
    const size_t base = (size_t)d0 * 4096 + h0 * 64 + wslab * 32;

#pragma unroll
    for (int i = 0; i < 12; i++) {
        int idx = i * 256 + tid;
        int ch = idx >> 3, f4 = (idx & 7) * 4;
        float4 v = *(const float4*)(x + (size_t)ch * 65536 + base + f4);
        float* d = sm + ch * 33 + f4;
        d[0] = v.x; d[1] = v.y; d[2] = v.z; d[3] = v.w;
    }
    __syncthreads();

    const int wi = tid >> 5, lane = tid & 31;
    const int d = (d0 + 14) & 15;
    const int h = (h0 + 60) & 63;
#pragma unroll
    for (int t = 0; t < 4; t++) {
        int wloc = wi + t * 8;
        float vals[12];
        float s = 0.f, ss = 0.f;
#pragma unroll
        for (int j = 0; j < 12; j++) {
            float v = sm[(lane + 32 * j) * 33 + wloc];
            vals[j] = v; s += v; ss += v * v;
        }
#pragma unroll
        for (int off = 16; off; off >>= 1) {
            s  += __shfl_xor_sync(0xffffffffu, s,  off);
            ss += __shfl_xor_sync(0xffffffffu, ss, off);
        }
        float mean = s * (1.0f / CDIM);
        float var  = ss * (1.0f / CDIM) - mean * mean;
        float rstd = rsqrtf(var + 1e-5f);
        int w = (wslab * 32 + wloc + 60) & 63;
        int n = token_index(d, h, w);
        bf16* op = out + (size_t)n * CDIM;
#pragma unroll
        for (int j = 0; j < 12; j++) {
            int ch = lane + 32 * j;
            float r = (vals[j] - mean) * rstd * gam[ch] + bet[ch];
            op[ch] = __float2bfloat16(r);
        }
    }
}

// ---------------- weight transposes ------------------------------------------
__global__ void transpose_kernel(const float* __restrict__ src,
                                 bf16* __restrict__ dst, int K, int N) {
    __shared__ float tile[32][33];
    int n0 = blockIdx.x * 32, k0 = blockIdx.y * 32;
    int tx = threadIdx.x & 31, ty = threadIdx.x >> 5;
#pragma unroll
    for (int i = ty; i < 32; i += 8)
        tile[i][tx] = src[(size_t)(k0 + i) * N + n0 + tx];
    __syncthreads();
#pragma unroll
    for (int i = ty; i < 32; i += 8)
        dst[(size_t)(n0 + i) * K + k0 + tx] = __float2bfloat16(tile[tx][i]);
}

__global__ void transpose_qkv_kernel(const float* __restrict__ Wq,
                                     const float* __restrict__ Wk,
                                     const float* __restrict__ Wv,
                                     bf16* __restrict__ dst) {
    __shared__ float tile[32][33];
    const float* src = (blockIdx.z == 0) ? Wq : (blockIdx.z == 1) ? Wk : Wv;
    bf16* d = dst + (size_t)blockIdx.z * 147456;
    int n0 = blockIdx.x * 32, k0 = blockIdx.y * 32;
    int tx = threadIdx.x & 31, ty = threadIdx.x >> 5;
#pragma unroll
    for (int i = ty; i < 32; i += 8)
        tile[i][tx] = src[(size_t)(k0 + i) * CDIM + n0 + tx];
    __syncthreads();
#pragma unroll
    for (int i = ty; i < 32; i += 8)
        d[(size_t)(n0 + i) * CDIM + k0 + tx] = __float2bfloat16(tile[tx][i]);
}

// ---------------- reverse window partition + shift ---------------------------
__global__ void window_scatter_kernel(const float* __restrict__ y,
                                      float* __restrict__ out) {
    __shared__ float sm[32][65];
    const int c0 = blockIdx.x * 32;
    const int h0 = blockIdx.y;
    const int d0 = blockIdx.z;
    const int tid = threadIdx.x;
    {
        int w0 = tid >> 2;
        int cg = (tid & 3) * 8;
        int d = (d0 + 14) & 15;
        int h = (h0 + 60) & 63;
        int w = (w0 + 60) & 63;
        int n = token_index(d, h, w);
        const float* ip = y + (size_t)n * CDIM + c0 + cg;
        float4 a = *(const float4*)ip;
        float4 b = *(const float4*)(ip + 4);
        sm[cg + 0][w0] = a.x; sm[cg + 1][w0] = a.y;
        sm[cg + 2][w0] = a.z; sm[cg + 3][w0] = a.w;
        sm[cg + 4][w0] = b.x; sm[cg + 5][w0] = b.y;
        sm[cg + 6][w0] = b.z; sm[cg + 7][w0] = b.w;
    }
    __syncthreads();
    int cl = tid >> 4;
    int v4 = (tid & 15) * 4;
    float* op = out + (size_t)(c0 + cl) * 65536 + d0 * 4096 + h0 * 64 + v4;
    float4 o;
    o.x = sm[cl][v4 + 0]; o.y = sm[cl][v4 + 1];
    o.z = sm[cl][v4 + 2]; o.w = sm[cl][v4 + 3];
    *(float4*)op = o;
    float4 p;
    p.x = sm[cl + 16][v4 + 0]; p.y = sm[cl + 16][v4 + 1];
    p.z = sm[cl + 16][v4 + 2]; p.w = sm[cl + 16][v4 + 3];
    *(float4*)(op + (size_t)16 * 65536) = p;
}

// ---------------- layernorm 2 ------------------------------------------------
__global__ void ln_kernel(const float* __restrict__ x,
                          const float* __restrict__ gam,
                          const float* __restrict__ bet,
                          bf16* __restrict__ out) {
    int warp = threadIdx.x >> 5;
    int lane = threadIdx.x & 31;
    size_t n = (size_t)blockIdx.x * 8 + warp;
    const float4* xr = (const float4*)(x + n * CDIM);
    float4 v[3];
    float s = 0.f, ss = 0.f;
#pragma unroll
    for (int i = 0; i < 3; i++) {
        v[i] = xr[i * 32 + lane];
        s += v[i].x + v[i].y + v[i].z + v[i].w;
        ss += v[i].x * v[i].x + v[i].y * v[i].y + v[i].z * v[i].z + v[i].w * v[i].w;
    }
#pragma unroll
    for (int off = 16; off; off >>= 1) {
        s  += __shfl_xor_sync(0xffffffffu, s,  off);
        ss += __shfl_xor_sync(0xffffffffu, ss, off);
    }
    float mean = s * (1.0f / CDIM);
    float var  = ss * (1.0f / CDIM) - mean * mean;
    float rstd = rsqrtf(var + 1e-5f);
    const float4* G = (const float4*)gam;
    const float4* B = (const float4*)bet;
    uint2* o = (uint2*)(out + n * CDIM);
#pragma unroll
    for (int i = 0; i < 3; i++) {
        float4 g = G[i * 32 + lane];
        float4 b = B[i * 32 + lane];
        float4 r;
        r.x = (v[i].x - mean) * rstd * g.x + b.x;
        r.y = (v[i].y - mean) * rstd * g.y + b.y;
        r.z = (v[i].z - mean) * rstd * g.z + b.z;
        r.w = (v[i].w - mean) * rstd * g.w + b.w;
        o[i * 32 + lane] = pack4bf(r);
    }
}

// ---------------- BF16 GEMM core: k64 stages, XOR swizzle, 3 buffers ---------
// Buffer: 128 rows x 128B (64 bf16), chunk16B swizzled by (chunk ^ (row&7)).
// One __syncthreads per k64 stage; buffer rotation compile-time (nk % 3 == 0).
#define BUFB 16384
#define GSMEM (6 * BUFB)   // 98304 B: sA[3] + sB[3]

__device__ __forceinline__ void mma_tile(const bf16* __restrict__ A,
                                         const bf16* __restrict__ Bt,
                                         int K, int rowBase, int colBase,
                                         float acc[4][4][4]) {
    char* sAc = s_dyn;
    char* sBc = s_dyn + 3 * BUFB;
    const int tid = threadIdx.x;
    const int nk = K >> 6;                 // 6 or 24, divisible by 3
    const int wid = tid >> 5, lane = tid & 31;
    const int wr = (wid >> 2) * 64, wc = (wid & 3) * 32;
    const int arow = wr + (lane & 15);
    const int ach = lane >> 4;                         // 0/1: k-half
    const int brow = wc + (lane & 7) + ((lane >> 4) << 3);
    const int bch = (lane >> 3) & 1;

    uint32_t aBase[3], bBase[3];
#pragma unroll
    for (int i = 0; i < 3; i++) {
        aBase[i] = smem_u32(sAc + i * BUFB);
        bBase[i] = smem_u32(sBc + i * BUFB);
    }
    const bf16* Ag = A + (size_t)rowBase * K;
    const bf16* Bg = Bt + (size_t)colBase * K;

#pragma unroll
    for (int mt = 0; mt < 4; mt++)
#pragma unroll
        for (int nt = 0; nt < 4; nt++)
#pragma unroll
            for (int f = 0; f < 4; f++) acc[mt][nt][f] = 0.f;

    auto stage = [&](int ks, uint32_t aD, uint32_t bD) {
#pragma unroll
        for (int i = 0; i < 4; i++) {
            int c = i * 256 + tid;        // 0..1023 chunks of 16B
            int r = c >> 3, ch = c & 7;
            uint32_t so = (uint32_t)(r * 128 + ((ch ^ (r & 7)) * 16));
            size_t go = (size_t)r * K + ks * 64 + ch * 8;
            cp_async16(aD + so, Ag + go);
            cp_async16(bD + so, Bg + go);
        }
        cp_commit();
    };

    stage(0, aBase[0], bBase[0]);
    stage(1, aBase[1], bBase[1]);

    for (int k = 0; k < nk; k += 3) {
#pragma unroll
        for (int j = 0; j < 3; j++) {
            const int kk = k + j;
            const int pb = (j + 2) % 3;    // compile-time per unrolled j
            if (kk == nk - 1) cp_wait<0>(); else cp_wait<1>();
            __syncthreads();
            if (kk + 2 < nk) stage(kk + 2, aBase[pb], bBase[pb]);
            const uint32_t aB = aBase[j], bB = bBase[j];
#pragma unroll
            for (int kb = 0; kb < 4; kb++) {
                uint32_t af[4][4], bb[2][4];
#pragma unroll
                for (int mt = 0; mt < 4; mt++) {
                    int row = arow + mt * 16;
                    int ch = 2 * kb + ach;
                    ldm_x4(af[mt], aB + (uint32_t)(row * 128 +
                             ((ch ^ (row & 7)) * 16)));
                }
#pragma unroll
                for (int nh = 0; nh < 2; nh++) {
                    int row = brow + nh * 16;
                    int ch = 2 * kb + bch;
                    ldm_x4(bb[nh], bB + (uint32_t)(row * 128 +
                             ((ch ^ (row & 7)) * 16)));
                }
#pragma unroll
                for (int mt = 0; mt < 4; mt++)
#pragma unroll
                    for (int nt = 0; nt < 4; nt++)
                        mma_bf16(acc[mt][nt], af[mt], &bb[nt >> 1][(nt & 1) * 2]);
            }
        }
    }
}

// ---- QKV GEMM: scatter bf16 to [win][head][t][64] ---------------------------
__global__ __launch_bounds__(256, 2)
void mm_qkv(const bf16* __restrict__ hb, const bf16* __restrict__ wt,
            const float* __restrict__ bq, const float* __restrict__ bk,
            const float* __restrict__ bv,
            bf16* __restrict__ q, bf16* __restrict__ k,
            bf16* __restrict__ v) {
    int g = blockIdx.z;
    const bf16* Bt = wt + (size_t)g * 147456;
    const float* bias = (g == 0) ? bq : (g == 1) ? bk : bv;
    bf16* out = (g == 0) ? q : (g == 1) ? k : v;
    int rowBase = blockIdx.y * 128, colBase = blockIdx.x * 128;

    float acc[4][4][4];
    mma_tile(hb, Bt, CDIM, rowBase, colBase, acc);

    const int lane = threadIdx.x & 31, wid = threadIdx.x >> 5;
    const int gid = lane >> 2, tig = lane & 3;
    const int wr = (wid >> 2) * 64, wc = (wid & 3) * 32;
#pragma unroll
    for (int mt = 0; mt < 4; mt++) {
        int r0 = rowBase + wr + mt * 16 + gid;
#pragma unroll
        for (int nt = 0; nt < 4; nt++) {
            int c = colBase + wc + nt * 8 + 2 * tig;
            int head = c >> 6, dd = c & 63;
            float bx = bias[c], by = bias[c + 1];
#pragma unroll
            for (int hh = 0; hh < 2; hh++) {
                int r = r0 + hh * 8;
                int win = r >> 8, t = r & 255;
                bf162 o = __floats2bfloat162_rn(acc[mt][nt][2 * hh] + bx,
                                                acc[mt][nt][2 * hh + 1] + by);
                *(bf162*)(out + (size_t)win * 98304 + head * 16384 +
                          t * 64 + dd) = o;
            }
        }
    }
}

// ---- out-proj GEMM + bias + residual read straight from x -------------------
__global__ __launch_bounds__(256, 2)
void mm_biasres_x(const bf16* __restrict__ A, const bf16* __restrict__ Bt,
                  const float* __restrict__ bias, const float* __restrict__ x,
                  float* __restrict__ out) {
    int rowBase = blockIdx.y * 128, colBase = blockIdx.x * 128;
    float acc[4][4][4];
    mma_tile(A, Bt, CDIM, rowBase, colBase, acc);

    const int lane = threadIdx.x & 31, wid = threadIdx.x >> 5;
    const int gid = lane >> 2, tig = lane & 3;
    const int wr = (wid >> 2) * 64, wc = (wid & 3) * 32;
#pragma unroll
    for (int mt = 0; mt < 4; mt++) {
        int r0 = rowBase + wr + mt * 16 + gid;
#pragma unroll
        for (int hh = 0; hh < 2; hh++) {
            int n = r0 + hh * 8;
            size_t sp = (size_t)token_spatial(n);
#pragma unroll
            for (int nt = 0; nt < 4; nt++) {
                int c = colBase + wc + nt * 8 + 2 * tig;
                float rx = x[(size_t)c * 65536 + sp];
                float ry = x[(size_t)(c + 1) * 65536 + sp];
                float2 o = make_float2(acc[mt][nt][2 * hh] + bias[c] + rx,
                                       acc[mt][nt][2 * hh + 1] + bias[c + 1] + ry);
                *(float2*)(out + (size_t)n * CDIM + c) = o;
            }
        }
    }
}

// ---- GEMM + bias + residual (token-major fp32 residual) ---------------------
__global__ __launch_bounds__(256, 2)
void mm_biasres(const bf16* __restrict__ A, const bf16* __restrict__ Bt,
                const float* __restrict__ bias, const float* __restrict__ res,
                float* __restrict__ out, int K) {
    int rowBase = blockIdx.y * 128, colBase = blockIdx.x * 128;
    float acc[4][4][4];
    mma_tile(A, Bt, K, rowBase, colBase, acc);

    const int lane = threadIdx.x & 31, wid = threadIdx.x >> 5;
    const int gid = lane >> 2, tig = lane & 3;
    const int wr = (wid >> 2) * 64, wc = (wid & 3) * 32;
#pragma unroll
    for (int mt = 0; mt < 4; mt++) {
        int r0 = rowBase + wr + mt * 16 + gid;
#pragma unroll
        for (int nt = 0; nt < 4; nt++) {
            int c = colBase + wc + nt * 8 + 2 * tig;
            float bx = bias[c], by = bias[c + 1];
#pragma unroll
            for (int hh = 0; hh < 2; hh++) {
                size_t off = (size_t)(r0 + hh * 8) * CDIM + c;
                float2 rr = *(const float2*)(res + off);
                float2 o = make_float2(acc[mt][nt][2 * hh] + bx + rr.x,
                                       acc[mt][nt][2 * hh + 1] + by + rr.y);
                *(float2*)(out + off) = o;
            }
        }
    }
}

// ---- GEMM + bias + exact GELU (bf16 out, N=1536) ----------------------------
__device__ __forceinline__ float gelu_f(float v) {
    return 0.5f * v * (1.0f + erff(v * 0.70710678118654752440f));
}

__global__ __launch_bounds__(256, 2)
void mm_gelu(const bf16* __restrict__ A, const bf16* __restrict__ Bt,
             const float* __restrict__ bias, bf16* __restrict__ out) {
    int rowBase = blockIdx.y * 128, colBase = blockIdx.x * 128;
    float acc[4][4][4];
    mma_tile(A, Bt, CDIM, rowBase, colBase, acc);

    const int lane = threadIdx.x & 31, wid = threadIdx.x >> 5;
    const int gid = lane >> 2, tig = lane & 3;
    const int wr = (wid >> 2) * 64, wc = (wid & 3) * 32;
#pragma unroll
    for (int mt = 0; mt < 4; mt++) {
        int r0 = rowBase + wr + mt * 16 + gid;
#pragma unroll
        for (int nt = 0; nt < 4; nt++) {
            int c = colBase + wc + nt * 8 + 2 * tig;
            float bx = bias[c], by = bias[c + 1];
#pragma unroll
            for (int hh = 0; hh < 2; hh++) {
                size_t off = (size_t)(r0 + hh * 8) * MLPD + c;
                bf162 o = __floats2bfloat162_rn(
                    gelu_f(acc[mt][nt][2 * hh] + bx),
                    gelu_f(acc[mt][nt][2 * hh + 1] + by));
                *(bf162*)(out + off) = o;
            }
        }
    }
}

// ---------------- attention: bf16 flash, one CTA per (window, head) ----------
#define AST 88
#define ATT_SMEM (3 * 256 * AST * 2)

__global__ __launch_bounds__(256, 1)
void attn_mma(const bf16* __restrict__ q, const bf16* __restrict__ k,
              const bf16* __restrict__ v, bf16* __restrict__ out) {
    bf16* Kb = (bf16*)s_dyn;
    bf16* Vb = Kb + 256 * AST;
    bf16* Pb = Vb + 256 * AST;
    const int wh = blockIdx.x;
    const size_t base = (size_t)wh * 16384;
    const int tid = threadIdx.x;
    const int wid = tid >> 5, lane = tid & 31;
    const int gid = lane >> 2, tig = lane & 3;
    const int qr = wid * 32;
    bf16* Pw = Pb + wid * 32 * AST;
    const uint32_t KbB = smem_u32(Kb), VbB = smem_u32(Vb);
    const uint32_t PwB = smem_u32(Pw), PbB = smem_u32(Pb);

    {
        const uint4* Kg = (const uint4*)(k + base + (size_t)tid * 64);
        const uint4* Vg = (const uint4*)(v + base + (size_t)tid * 64);
        const uint4* Qg = (const uint4*)(q + base + (size_t)tid * 64);
        uint4* Kd = (uint4*)(Kb + tid * AST);
        uint4* Vd = (uint4*)(Vb + tid * AST);
        uint4* Qd = (uint4*)(Pb + tid * AST);
        bf162 sc = __float2bfloat162_rn(0.125f);
#pragma unroll
        for (int i = 0; i < 8; i++) {
            Kd[i] = Kg[i];
            Vd[i] = Vg[i];
            uint4 t = Qg[i];
            bf162* tp = (bf162*)&t;
#pragma unroll
            for (int j = 0; j < 4; j++) tp[j] = __hmul2(tp[j], sc);
            Qd[i] = t;
        }
    }
    __syncthreads();

    uint32_t qf[2][4][4];
#pragma unroll
    for (int mt = 0; mt < 2; mt++)
#pragma unroll
        for (int ks = 0; ks < 4; ks++)
            ldm_x4(qf[mt][ks], PbB + (uint32_t)(((qr + mt * 16 + (lane & 15)) * AST +
                     ks * 16 + (lane >> 4) * 8) * 2));
    __syncthreads();

    float oacc[2][8][4];
#pragma unroll
    for (int mt = 0; mt < 2; mt++)
#pragma unroll
        for (int nt = 0; nt < 8; nt++)
#pragma unroll
            for (int f = 0; f < 4; f++) oacc[mt][nt][f] = 0.f;
    float mrow[2][2] = {{-1e30f, -1e30f}, {-1e30f, -1e30f}};
    float lrow[2][2] = {{0.f, 0.f}, {0.f, 0.f}};

    const int kbrow = (lane & 7) + ((lane >> 4) << 3);
    const int kbhalf = ((lane >> 3) & 1) * 8;
    const int vrow = (lane & 7) + (((lane >> 3) & 1) << 3);
    const int vdim = (lane >> 4) * 8;

    for (int jb = 0; jb < 4; jb++) {
        float sacc[2][8][4];
#pragma unroll
        for (int mt = 0; mt < 2; mt++)
#pragma unroll
            for (int nt = 0; nt < 8; nt++)
#pragma unroll
                for (int f = 0; f < 4; f++) sacc[mt][nt][f] = 0.f;
#pragma unroll
        for (int ks = 0; ks < 4; ks++) {
            uint32_t kb4[4][4];
#pragma unroll
            for (int np = 0; np < 4; np++)
                ldm_x4(kb4[np], KbB + (uint32_t)(((jb * 64 + np * 16 + kbrow) * AST +
                         ks * 16 + kbhalf) * 2));
#pragma unroll
            for (int mt = 0; mt < 2; mt++)
#pragma unroll
                for (int nt = 0; nt < 8; nt++)
                    mma_bf16(sacc[mt][nt], qf[mt][ks], &kb4[nt >> 1][(nt & 1) * 2]);
        }

        __syncwarp();
#pragma unroll
        for (int mt = 0; mt < 2; mt++)
#pragma unroll
            for (int hh = 0; hh < 2; hh++) {
                float bm = -1e30f;
#pragma unroll
                for (int nt = 0; nt < 8; nt++) {
                    bm = fmaxf(bm, sacc[mt][nt][2 * hh]);
                    bm = fmaxf(bm, sacc[mt][nt][2 * hh + 1]);
                }
                bm = fmaxf(bm, __shfl_xor_sync(0xffffffffu, bm, 1));
                bm = fmaxf(bm, __shfl_xor_sync(0xffffffffu, bm, 2));
                float mn = fmaxf(mrow[mt][hh], bm);
                float scale = __expf(mrow[mt][hh] - mn);
                mrow[mt][hh] = mn;
                lrow[mt][hh] *= scale;
#pragma unroll
                for (int nt = 0; nt < 8; nt++) {
                    oacc[mt][nt][2 * hh]     *= scale;
                    oacc[mt][nt][2 * hh + 1] *= scale;
                }
                float psum = 0.f;
                int row = mt * 16 + gid + hh * 8;
#pragma unroll
                for (int nt = 0; nt < 8; nt++) {
                    float p0 = __expf(sacc[mt][nt][2 * hh]     - mn);
                    float p1 = __expf(sacc[mt][nt][2 * hh + 1] - mn);
                    psum += p0 + p1;
                    *(bf162*)(Pw + row * AST + nt * 8 + 2 * tig) =
                        __floats2bfloat162_rn(p0, p1);
                }
                psum += __shfl_xor_sync(0xffffffffu, psum, 1);
                psum += __shfl_xor_sync(0xffffffffu, psum, 2);
                lrow[mt][hh] += psum;
            }
        __syncwarp();

#pragma unroll
        for (int ks = 0; ks < 4; ks++) {
            uint32_t pf[2][4], vb4[4][4];
#pragma unroll
            for (int mt = 0; mt < 2; mt++)
                ldm_x4(pf[mt], PwB + (uint32_t)(((mt * 16 + (lane & 15)) * AST +
                         ks * 16 + (lane >> 4) * 8) * 2));
#pragma unroll
            for (int nb = 0; nb < 4; nb++)
                ldm_x4_t(vb4[nb], VbB + (uint32_t)(((jb * 64 + ks * 16 + vrow) * AST +
                           nb * 16 + vdim) * 2));
#pragma unroll
            for (int mt = 0; mt < 2; mt++)
#pragma unroll
                for (int nt = 0; nt < 8; nt++)
                    mma_bf16(oacc[mt][nt], pf[mt], &vb4[nt >> 1][(nt & 1) * 2]);
        }
    }

    const int win = wh / 6, head = wh % 6;
#pragma unroll
    for (int mt = 0; mt < 2; mt++)
#pragma unroll
        for (int hh = 0; hh < 2; hh++) {
            float inv = 1.0f / lrow[mt][hh];
            int row = qr + mt * 16 + gid + hh * 8;
            bf16* op = out + ((size_t)win * 256 + row) * CDIM + head * 64;
#pragma unroll
            for (int nt = 0; nt < 8; nt++) {
                bf162 o = __floats2bfloat162_rn(
                    oacc[mt][nt][2 * hh] * inv,
                    oacc[mt][nt][2 * hh + 1] * inv);
                *(bf162*)(op + nt * 8 + 2 * tig) = o;
            }
        }
}

// ---------------------------------------------------------------------------
extern "C" void kernel_launch(void* const* d_in, const int* in_sizes, int n_in,
                              void* d_out, int out_size) {
    (void)in_sizes; (void)n_in; (void)out_size;
    const float* x   = (const float*)d_in[0];
    const float* Wq  = (const float*)d_in[1];
    const float* bq  = (const float*)d_in[2];
    const float* Wk  = (const float*)d_in[3];
    const float* bk  = (const float*)d_in[4];
    const float* Wv  = (const float*)d_in[5];
    const float* bv  = (const float*)d_in[6];
    const float* Wo  = (const float*)d_in[7];
    const float* bo  = (const float*)d_in[8];
    const float* g1  = (const float*)d_in[9];
    const float* be1 = (const float*)d_in[10];
    const float* g2  = (const float*)d_in[11];
    const float* be2 = (const float*)d_in[12];
    const float* W1  = (const float*)d_in[13];
    const float* B1  = (const float*)d_in[14];
    const float* W2  = (const float*)d_in[15];
    const float* B2  = (const float*)d_in[16];
    float* out = (float*)d_out;

    float *x2, *yb;
    bf16 *hb, *qb, *kb, *vb, *att, *mlp, *wt;
    cudaGetSymbolAddress((void**)&hb,  g_h);
    cudaGetSymbolAddress((void**)&qb,  g_q);
    cudaGetSymbolAddress((void**)&kb,  g_k);
    cudaGetSymbolAddress((void**)&vb,  g_v);
    cudaGetSymbolAddress((void**)&att, g_att);
    cudaGetSymbolAddress((void**)&x2,  g_x2);
    cudaGetSymbolAddress((void**)&mlp, g_mlp);
    cudaGetSymbolAddress((void**)&yb,  g_y);
    cudaGetSymbolAddress((void**)&wt,  g_wt);

    cudaFuncSetAttribute(ln1x_kernel,
                         cudaFuncAttributeMaxDynamicSharedMemorySize, LN1_SMEM);
    cudaFuncSetAttribute(attn_mma,
                         cudaFuncAttributeMaxDynamicSharedMemorySize, ATT_SMEM);
    cudaFuncSetAttribute(mm_qkv,
                         cudaFuncAttributeMaxDynamicSharedMemorySize, GSMEM);
    cudaFuncSetAttribute(mm_biasres_x,
                         cudaFuncAttributeMaxDynamicSharedMemorySize, GSMEM);
    cudaFuncSetAttribute(mm_biasres,
                         cudaFuncAttributeMaxDynamicSharedMemorySize, GSMEM);
    cudaFuncSetAttribute(mm_gelu,
                         cudaFuncAttributeMaxDynamicSharedMemorySize, GSMEM);

    // 1) fused shift + window-gather + LN1 -> hb bf16
    ln1x_kernel<<<dim3(2, 64, 16), 256, LN1_SMEM>>>(x, g1, be1, hb);
    // 2) QKV weight transpose
    transpose_qkv_kernel<<<dim3(12, 12, 3), 256>>>(Wq, Wk, Wv, wt);
    // 3) Wo transpose
    transpose_kernel<<<dim3(12, 12), 256>>>(Wo, wt + 442368, CDIM, CDIM);
    // 4) QKV projections (profiled launch)
    mm_qkv<<<dim3(3, 512, 3), 256, GSMEM>>>(hb, wt, bq, bk, bv, qb, kb, vb);
    // 5-6) MLP weight transposes
    transpose_kernel<<<dim3(48, 12), 256>>>(W1, wt + 589824,  CDIM, MLPD);
    transpose_kernel<<<dim3(12, 48), 256>>>(W2, wt + 1179648, MLPD, CDIM);
    // 7) windowed attention (bf16 flash)
    attn_mma<<<1536, 256, ATT_SMEM>>>(qb, kb, vb, att);
    // 8) output projection + bias + residual-from-x -> x2 fp32
    mm_biasres_x<<<dim3(3, 512), 256, GSMEM>>>(att, wt + 442368, bo, x, x2);
    // 9) LN2 -> bf16
    ln_kernel<<<8192, 256>>>(x2, g2, be2, hb);
    // 10) MLP up + GELU -> bf16
    mm_gelu<<<dim3(12, 512), 256, GSMEM>>>(hb, wt + 589824, B1, mlp);
    // 11) MLP down + residual -> fp32
    mm_biasres<<<dim3(3, 512), 256, GSMEM>>>(mlp, wt + 1179648, B2, x2, yb, MLPD);
    // 12) reverse window partition + shift
    window_scatter_kernel<<<dim3(12, 64, 16), 256>>>(yb, out);
}

// round 14
// speedup vs baseline: 2.3009x; 1.0195x over previous
#include <cuda_runtime.h>
#include <cuda_bf16.h>
#include <math.h>
#include <stdint.h>

// ---------------------------------------------------------------------------
// SwinBlock3D: bf16 mma.sync GEMMs (k64 stages, XOR-swizzled smem, 3-buffer
// cp.async pipeline) + bf16 flash attention. LN1 fused with shift+gather;
// out-proj residual from x; MLP-down epilogue scatters straight to output.
// x(1,384,16,64,64) HEADS=6 MLP=1536
// ---------------------------------------------------------------------------

#define NTOK 65536
#define CDIM 384
#define MLPD 1536

typedef __nv_bfloat16 bf16;
typedef __nv_bfloat162 bf162;

__device__ bf16  g_h  [(size_t)NTOK * CDIM];
__device__ bf16  g_q  [(size_t)NTOK * CDIM];
__device__ bf16  g_k  [(size_t)NTOK * CDIM];
__device__ bf16  g_v  [(size_t)NTOK * CDIM];
__device__ bf16  g_att[(size_t)NTOK * CDIM];
__device__ float g_x2 [(size_t)NTOK * CDIM];
__device__ bf16  g_mlp[(size_t)NTOK * MLPD];
__device__ bf16  g_wt [1769472];

// ---------------- helpers ----------------------------------------------------
__device__ __forceinline__ uint32_t smem_u32(const void* p) {
    uint32_t a;
    asm("{ .reg .u64 t; cvta.to.shared.u64 t, %1; cvt.u32.u64 %0, t; }"
        : "=r"(a) : "l"(p));
    return a;
}
__device__ __forceinline__ void cp_async16(uint32_t s, const void* g) {
    asm volatile("cp.async.cg.shared.global [%0], [%1], 16;" :: "r"(s), "l"(g));
}
__device__ __forceinline__ void cp_commit() {
    asm volatile("cp.async.commit_group;");
}
template<int N> __device__ __forceinline__ void cp_wait() {
    asm volatile("cp.async.wait_group %0;" :: "n"(N));
}
__device__ __forceinline__ void ldm_x4(uint32_t r[4], uint32_t addr) {
    asm volatile("ldmatrix.sync.aligned.m8n8.x4.shared.b16 {%0,%1,%2,%3}, [%4];"
                 : "=r"(r[0]), "=r"(r[1]), "=r"(r[2]), "=r"(r[3]) : "r"(addr));
}
__device__ __forceinline__ void ldm_x4_t(uint32_t r[4], uint32_t addr) {
    asm volatile("ldmatrix.sync.aligned.m8n8.x4.trans.shared.b16 {%0,%1,%2,%3}, [%4];"
                 : "=r"(r[0]), "=r"(r[1]), "=r"(r[2]), "=r"(r[3]) : "r"(addr));
}
__device__ __forceinline__ void mma_bf16(float c[4], const uint32_t a[4],
                                         const uint32_t b[2]) {
    asm volatile(
        "mma.sync.aligned.m16n8k16.row.col.f32.bf16.bf16.f32 "
        "{%0,%1,%2,%3}, {%4,%5,%6,%7}, {%8,%9}, {%0,%1,%2,%3};"
        : "+f"(c[0]), "+f"(c[1]), "+f"(c[2]), "+f"(c[3])
        : "r"(a[0]), "r"(a[1]), "r"(a[2]), "r"(a[3]), "r"(b[0]), "r"(b[1]));
}
__device__ __forceinline__ uint2 pack4bf(float4 r) {
    bf162 lo = __floats2bfloat162_rn(r.x, r.y);
    bf162 hi = __floats2bfloat162_rn(r.z, r.w);
    uint2 u;
    u.x = *(uint32_t*)&lo;
    u.y = *(uint32_t*)&hi;
    return u;
}

extern __shared__ char s_dyn[];

__device__ __forceinline__ int token_index(int d, int h, int w) {
    int win = ((d >> 2) * 8 + (h >> 3)) * 8 + (w >> 3);
    int tok = ((d & 3) << 6) + ((h & 7) << 3) + (w & 7);
    return (win << 8) + tok;
}
__device__ __forceinline__ int token_spatial(int n) {
    int win = n >> 8, tok = n & 255;
    int d = ((win >> 6) << 2) | (tok >> 6);
    int h = (((win >> 3) & 7) << 3) | ((tok >> 3) & 7);
    int w = ((win & 7) << 3) | (tok & 7);
    int d0 = (d + 2) & 15, h0 = (h + 4) & 63, w0 = (w + 4) & 63;
    return d0 * 4096 + h0 * 64 + w0;
}

// ---------------- fused shift + window-gather + LN1 (x -> hb bf16) -----------
#define LN1_SMEM (384 * 33 * 4)

__global__ void ln1x_kernel(const float* __restrict__ x,
                            const float* __restrict__ gam,
                            const float* __restrict__ bet,
                            bf16* __restrict__ out) {
    float* sm = (float*)s_dyn;
    const int wslab = blockIdx.x;
    const int h0 = blockIdx.y;
    const int d0 = blockIdx.z;
    const int tid = threadIdx.x;
    const size_t base = (size_t)d0 * 4096 + h0 * 64 + wslab * 32;

#pragma unroll
    for (int i = 0; i < 12; i++) {
        int idx = i * 256 + tid;
        int ch = idx >> 3, f4 = (idx & 7) * 4;
        float4 v = *(const float4*)(x + (size_t)ch * 65536 + base + f4);
        float* d = sm + ch * 33 + f4;
        d[0] = v.x; d[1] = v.y; d[2] = v.z; d[3] = v.w;
    }
    __syncthreads();

    const int wi = tid >> 5, lane = tid & 31;
    const int d = (d0 + 14) & 15;
    const int h = (h0 + 60) & 63;
#pragma unroll
    for (int t = 0; t < 4; t++) {
        int wloc = wi + t * 8;
        float vals[12];
        float s = 0.f, ss = 0.f;
#pragma unroll
        for (int j = 0; j < 12; j++) {
            float v = sm[(lane + 32 * j) * 33 + wloc];
            vals[j] = v; s += v; ss += v * v;
        }
#pragma unroll
        for (int off = 16; off; off >>= 1) {
            s  += __shfl_xor_sync(0xffffffffu, s,  off);
            ss += __shfl_xor_sync(0xffffffffu, ss, off);
        }
        float mean = s * (1.0f / CDIM);
        float var  = ss * (1.0f / CDIM) - mean * mean;
        float rstd = rsqrtf(var + 1e-5f);
        int w = (wslab * 32 + wloc + 60) & 63;
        int n = token_index(d, h, w);
        bf16* op = out + (size_t)n * CDIM;
#pragma unroll
        for (int j = 0; j < 12; j++) {
            int ch = lane + 32 * j;
            float r = (vals[j] - mean) * rstd * gam[ch] + bet[ch];
            op[ch] = __float2bfloat16(r);
        }
    }
}

// ---------------- weight transposes ------------------------------------------
__global__ void transpose_kernel(const float* __restrict__ src,
                                 bf16* __restrict__ dst, int K, int N) {
    __shared__ float tile[32][33];
    int n0 = blockIdx.x * 32, k0 = blockIdx.y * 32;
    int tx = threadIdx.x & 31, ty = threadIdx.x >> 5;
#pragma unroll
    for (int i = ty; i < 32; i += 8)
        tile[i][tx] = src[(size_t)(k0 + i) * N + n0 + tx];
    __syncthreads();
#pragma unroll
    for (int i = ty; i < 32; i += 8)
        dst[(size_t)(n0 + i) * K + k0 + tx] = __float2bfloat16(tile[tx][i]);
}

__global__ void transpose_qkv_kernel(const float* __restrict__ Wq,
                                     const float* __restrict__ Wk,
                                     const float* __restrict__ Wv,
                                     bf16* __restrict__ dst) {
    __shared__ float tile[32][33];
    const float* src = (blockIdx.z == 0) ? Wq : (blockIdx.z == 1) ? Wk : Wv;
    bf16* d = dst + (size_t)blockIdx.z * 147456;
    int n0 = blockIdx.x * 32, k0 = blockIdx.y * 32;
    int tx = threadIdx.x & 31, ty = threadIdx.x >> 5;
#pragma unroll
    for (int i = ty; i < 32; i += 8)
        tile[i][tx] = src[(size_t)(k0 + i) * CDIM + n0 + tx];
    __syncthreads();
#pragma unroll
    for (int i = ty; i < 32; i += 8)
        d[(size_t)(n0 + i) * CDIM + k0 + tx] = __float2bfloat16(tile[tx][i]);
}

// ---------------- layernorm 2 ------------------------------------------------
__global__ void ln_kernel(const float* __restrict__ x,
                          const float* __restrict__ gam,
                          const float* __restrict__ bet,
                          bf16* __restrict__ out) {
    int warp = threadIdx.x >> 5;
    int lane = threadIdx.x & 31;
    size_t n = (size_t)blockIdx.x * 8 + warp;
    const float4* xr = (const float4*)(x + n * CDIM);
    float4 v[3];
    float s = 0.f, ss = 0.f;
#pragma unroll
    for (int i = 0; i < 3; i++) {
        v[i] = xr[i * 32 + lane];
        s += v[i].x + v[i].y + v[i].z + v[i].w;
        ss += v[i].x * v[i].x + v[i].y * v[i].y + v[i].z * v[i].z + v[i].w * v[i].w;
    }
#pragma unroll
    for (int off = 16; off; off >>= 1) {
        s  += __shfl_xor_sync(0xffffffffu, s,  off);
        ss += __shfl_xor_sync(0xffffffffu, ss, off);
    }
    float mean = s * (1.0f / CDIM);
    float var  = ss * (1.0f / CDIM) - mean * mean;
    float rstd = rsqrtf(var + 1e-5f);
    const float4* G = (const float4*)gam;
    const float4* B = (const float4*)bet;
    uint2* o = (uint2*)(out + n * CDIM);
#pragma unroll
    for (int i = 0; i < 3; i++) {
        float4 g = G[i * 32 + lane];
        float4 b = B[i * 32 + lane];
        float4 r;
        r.x = (v[i].x - mean) * rstd * g.x + b.x;
        r.y = (v[i].y - mean) * rstd * g.y + b.y;
        r.z = (v[i].z - mean) * rstd * g.z + b.z;
        r.w = (v[i].w - mean) * rstd * g.w + b.w;
        o[i * 32 + lane] = pack4bf(r);
    }
}

// ---------------- BF16 GEMM core: k64 stages, XOR swizzle, 3 buffers ---------
#define BUFB 16384
#define GSMEM (6 * BUFB)   // 98304 B: sA[3] + sB[3]

__device__ __forceinline__ void mma_tile(const bf16* __restrict__ A,
                                         const bf16* __restrict__ Bt,
                                         int K, int rowBase, int colBase,
                                         float acc[4][4][4]) {
    char* sAc = s_dyn;
    char* sBc = s_dyn + 3 * BUFB;
    const int tid = threadIdx.x;
    const int nk = K >> 6;                 // 6 or 24, divisible by 3
    const int wid = tid >> 5, lane = tid & 31;
    const int wr = (wid >> 2) * 64, wc = (wid & 3) * 32;
    const int arow = wr + (lane & 15);
    const int ach = lane >> 4;
    const int brow = wc + (lane & 7) + ((lane >> 4) << 3);
    const int bch = (lane >> 3) & 1;

    uint32_t aBase[3], bBase[3];
#pragma unroll
    for (int i = 0; i < 3; i++) {
        aBase[i] = smem_u32(sAc + i * BUFB);
        bBase[i] = smem_u32(sBc + i * BUFB);
    }
    const bf16* Ag = A + (size_t)rowBase * K;
    const bf16* Bg = Bt + (size_t)colBase * K;

#pragma unroll
    for (int mt = 0; mt < 4; mt++)
#pragma unroll
        for (int nt = 0; nt < 4; nt++)
#pragma unroll
            for (int f = 0; f < 4; f++) acc[mt][nt][f] = 0.f;

    auto stage = [&](int ks, uint32_t aD, uint32_t bD) {
#pragma unroll
        for (int i = 0; i < 4; i++) {
            int c = i * 256 + tid;
            int r = c >> 3, ch = c & 7;
            uint32_t so = (uint32_t)(r * 128 + ((ch ^ (r & 7)) * 16));
            size_t go = (size_t)r * K + ks * 64 + ch * 8;
            cp_async16(aD + so, Ag + go);
            cp_async16(bD + so, Bg + go);
        }
        cp_commit();
    };

    stage(0, aBase[0], bBase[0]);
    stage(1, aBase[1], bBase[1]);

    for (int k = 0; k < nk; k += 3) {
#pragma unroll
        for (int j = 0; j < 3; j++) {
            const int kk = k + j;
            const int pb = (j + 2) % 3;
            if (kk == nk - 1) cp_wait<0>(); else cp_wait<1>();
            __syncthreads();
            if (kk + 2 < nk) stage(kk + 2, aBase[pb], bBase[pb]);
            const uint32_t aB = aBase[j], bB = bBase[j];
#pragma unroll
            for (int kb = 0; kb < 4; kb++) {
                uint32_t af[4][4], bb[2][4];
#pragma unroll
                for (int mt = 0; mt < 4; mt++) {
                    int row = arow + mt * 16;
                    int ch = 2 * kb + ach;
                    ldm_x4(af[mt], aB + (uint32_t)(row * 128 +
                             ((ch ^ (row & 7)) * 16)));
                }
#pragma unroll
                for (int nh = 0; nh < 2; nh++) {
                    int row = brow + nh * 16;
                    int ch = 2 * kb + bch;
                    ldm_x4(bb[nh], bB + (uint32_t)(row * 128 +
                             ((ch ^ (row & 7)) * 16)));
                }
#pragma unroll
                for (int mt = 0; mt < 4; mt++)
#pragma unroll
                    for (int nt = 0; nt < 4; nt++)
                        mma_bf16(acc[mt][nt], af[mt], &bb[nt >> 1][(nt & 1) * 2]);
            }
        }
    }
}

// ---- QKV GEMM: scatter bf16 to [win][head][t][64] ---------------------------
__global__ __launch_bounds__(256, 2)
void mm_qkv(const bf16* __restrict__ hb, const bf16* __restrict__ wt,
            const float* __restrict__ bq, const float* __restrict__ bk,
            const float* __restrict__ bv,
            bf16* __restrict__ q, bf16* __restrict__ k,
            bf16* __restrict__ v) {
    int g = blockIdx.z;
    const bf16* Bt = wt + (size_t)g * 147456;
    const float* bias = (g == 0) ? bq : (g == 1) ? bk : bv;
    bf16* out = (g == 0) ? q : (g == 1) ? k : v;
    int rowBase = blockIdx.y * 128, colBase = blockIdx.x * 128;

    float acc[4][4][4];
    mma_tile(hb, Bt, CDIM, rowBase, colBase, acc);

    const int lane = threadIdx.x & 31, wid = threadIdx.x >> 5;
    const int gid = lane >> 2, tig = lane & 3;
    const int wr = (wid >> 2) * 64, wc = (wid & 3) * 32;
#pragma unroll
    for (int mt = 0; mt < 4; mt++) {
        int r0 = rowBase + wr + mt * 16 + gid;
#pragma unroll
        for (int nt = 0; nt < 4; nt++) {
            int c = colBase + wc + nt * 8 + 2 * tig;
            int head = c >> 6, dd = c & 63;
            float bx = bias[c], by = bias[c + 1];
#pragma unroll
            for (int hh = 0; hh < 2; hh++) {
                int r = r0 + hh * 8;
                int win = r >> 8, t = r & 255;
                bf162 o = __floats2bfloat162_rn(acc[mt][nt][2 * hh] + bx,
                                                acc[mt][nt][2 * hh + 1] + by);
                *(bf162*)(out + (size_t)win * 98304 + head * 16384 +
                          t * 64 + dd) = o;
            }
        }
    }
}

// ---- out-proj GEMM + bias + residual read straight from x -------------------
__global__ __launch_bounds__(256, 2)
void mm_biasres_x(const bf16* __restrict__ A, const bf16* __restrict__ Bt,
                  const float* __restrict__ bias, const float* __restrict__ x,
                  float* __restrict__ out) {
    int rowBase = blockIdx.y * 128, colBase = blockIdx.x * 128;
    float acc[4][4][4];
    mma_tile(A, Bt, CDIM, rowBase, colBase, acc);

    const int lane = threadIdx.x & 31, wid = threadIdx.x >> 5;
    const int gid = lane >> 2, tig = lane & 3;
    const int wr = (wid >> 2) * 64, wc = (wid & 3) * 32;
#pragma unroll
    for (int mt = 0; mt < 4; mt++) {
        int r0 = rowBase + wr + mt * 16 + gid;
#pragma unroll
        for (int hh = 0; hh < 2; hh++) {
            int n = r0 + hh * 8;
            size_t sp = (size_t)token_spatial(n);
#pragma unroll
            for (int nt = 0; nt < 4; nt++) {
                int c = colBase + wc + nt * 8 + 2 * tig;
                float rx = x[(size_t)c * 65536 + sp];
                float ry = x[(size_t)(c + 1) * 65536 + sp];
                float2 o = make_float2(acc[mt][nt][2 * hh] + bias[c] + rx,
                                       acc[mt][nt][2 * hh + 1] + bias[c + 1] + ry);
                *(float2*)(out + (size_t)n * CDIM + c) = o;
            }
        }
    }
}

// ---- MLP-down GEMM + bias + residual + direct channel-major scatter ---------
__global__ __launch_bounds__(256, 2)
void mm_biasres_scatter(const bf16* __restrict__ A, const bf16* __restrict__ Bt,
                        const float* __restrict__ bias,
                        const float* __restrict__ res,
                        float* __restrict__ out, int K) {
    int rowBase = blockIdx.y * 128, colBase = blockIdx.x * 128;
    float acc[4][4][4];
    mma_tile(A, Bt, K, rowBase, colBase, acc);

    const int lane = threadIdx.x & 31, wid = threadIdx.x >> 5;
    const int gid = lane >> 2, tig = lane & 3;
    const int wr = (wid >> 2) * 64, wc = (wid & 3) * 32;
#pragma unroll
    for (int mt = 0; mt < 4; mt++) {
        int r0 = rowBase + wr + mt * 16 + gid;
#pragma unroll
        for (int hh = 0; hh < 2; hh++) {
            int n = r0 + hh * 8;
            size_t sp = (size_t)token_spatial(n);
            const float* rp = res + (size_t)n * CDIM;
#pragma unroll
            for (int nt = 0; nt < 4; nt++) {
                int c = colBase + wc + nt * 8 + 2 * tig;
                float2 rr = *(const float2*)(rp + c);
                out[(size_t)c * 65536 + sp] =
                    acc[mt][nt][2 * hh] + bias[c] + rr.x;
                out[(size_t)(c + 1) * 65536 + sp] =
                    acc[mt][nt][2 * hh + 1] + bias[c + 1] + rr.y;
            }
        }
    }
}

// ---- GEMM + bias + exact GELU (bf16 out, N=1536) ----------------------------
__device__ __forceinline__ float gelu_f(float v) {
    return 0.5f * v * (1.0f + erff(v * 0.70710678118654752440f));
}

__global__ __launch_bounds__(256, 2)
void mm_gelu(const bf16* __restrict__ A, const bf16* __restrict__ Bt,
             const float* __restrict__ bias, bf16* __restrict__ out) {
    int rowBase = blockIdx.y * 128, colBase = blockIdx.x * 128;
    float acc[4][4][4];
    mma_tile(A, Bt, CDIM, rowBase, colBase, acc);

    const int lane = threadIdx.x & 31, wid = threadIdx.x >> 5;
    const int gid = lane >> 2, tig = lane & 3;
    const int wr = (wid >> 2) * 64, wc = (wid & 3) * 32;
#pragma unroll
    for (int mt = 0; mt < 4; mt++) {
        int r0 = rowBase + wr + mt * 16 + gid;
#pragma unroll
        for (int nt = 0; nt < 4; nt++) {
            int c = colBase + wc + nt * 8 + 2 * tig;
            float bx = bias[c], by = bias[c + 1];
#pragma unroll
            for (int hh = 0; hh < 2; hh++) {
                size_t off = (size_t)(r0 + hh * 8) * MLPD + c;
                bf162 o = __floats2bfloat162_rn(
                    gelu_f(acc[mt][nt][2 * hh] + bx),
                    gelu_f(acc[mt][nt][2 * hh + 1] + by));
                *(bf162*)(out + off) = o;
            }
        }
    }
}

// ---------------- attention: bf16 flash, one CTA per (window, head) ----------
#define AST 88
#define ATT_SMEM (3 * 256 * AST * 2)

__global__ __launch_bounds__(256, 1)
void attn_mma(const bf16* __restrict__ q, const bf16* __restrict__ k,
              const bf16* __restrict__ v, bf16* __restrict__ out) {
    bf16* Kb = (bf16*)s_dyn;
    bf16* Vb = Kb + 256 * AST;
    bf16* Pb = Vb + 256 * AST;
    const int wh = blockIdx.x;
    const size_t base = (size_t)wh * 16384;
    const int tid = threadIdx.x;
    const int wid = tid >> 5, lane = tid & 31;
    const int gid = lane >> 2, tig = lane & 3;
    const int qr = wid * 32;
    bf16* Pw = Pb + wid * 32 * AST;
    const uint32_t KbB = smem_u32(Kb), VbB = smem_u32(Vb);
    const uint32_t PwB = smem_u32(Pw), PbB = smem_u32(Pb);

    {
        const uint4* Kg = (const uint4*)(k + base + (size_t)tid * 64);
        const uint4* Vg = (const uint4*)(v + base + (size_t)tid * 64);
        const uint4* Qg = (const uint4*)(q + base + (size_t)tid * 64);
        uint4* Kd = (uint4*)(Kb + tid * AST);
        uint4* Vd = (uint4*)(Vb + tid * AST);
        uint4* Qd = (uint4*)(Pb + tid * AST);
        bf162 sc = __float2bfloat162_rn(0.125f);
#pragma unroll
        for (int i = 0; i < 8; i++) {
            Kd[i] = Kg[i];
            Vd[i] = Vg[i];
            uint4 t = Qg[i];
            bf162* tp = (bf162*)&t;
#pragma unroll
            for (int j = 0; j < 4; j++) tp[j] = __hmul2(tp[j], sc);
            Qd[i] = t;
        }
    }
    __syncthreads();

    uint32_t qf[2][4][4];
#pragma unroll
    for (int mt = 0; mt < 2; mt++)
#pragma unroll
        for (int ks = 0; ks < 4; ks++)
            ldm_x4(qf[mt][ks], PbB + (uint32_t)(((qr + mt * 16 + (lane & 15)) * AST +
                     ks * 16 + (lane >> 4) * 8) * 2));
    __syncthreads();

    float oacc[2][8][4];
#pragma unroll
    for (int mt = 0; mt < 2; mt++)
#pragma unroll
        for (int nt = 0; nt < 8; nt++)
#pragma unroll
            for (int f = 0; f < 4; f++) oacc[mt][nt][f] = 0.f;
    float mrow[2][2] = {{-1e30f, -1e30f}, {-1e30f, -1e30f}};
    float lrow[2][2] = {{0.f, 0.f}, {0.f, 0.f}};

    const int kbrow = (lane & 7) + ((lane >> 4) << 3);
    const int kbhalf = ((lane >> 3) & 1) * 8;
    const int vrow = (lane & 7) + (((lane >> 3) & 1) << 3);
    const int vdim = (lane >> 4) * 8;

    for (int jb = 0; jb < 4; jb++) {
        float sacc[2][8][4];
#pragma unroll
        for (int mt = 0; mt < 2; mt++)
#pragma unroll
            for (int nt = 0; nt < 8; nt++)
#pragma unroll
                for (int f = 0; f < 4; f++) sacc[mt][nt][f] = 0.f;
#pragma unroll
        for (int ks = 0; ks < 4; ks++) {
            uint32_t kb4[4][4];
#pragma unroll
            for (int np = 0; np < 4; np++)
                ldm_x4(kb4[np], KbB + (uint32_t)(((jb * 64 + np * 16 + kbrow) * AST +
                         ks * 16 + kbhalf) * 2));
#pragma unroll
            for (int mt = 0; mt < 2; mt++)
#pragma unroll
                for (int nt = 0; nt < 8; nt++)
                    mma_bf16(sacc[mt][nt], qf[mt][ks], &kb4[nt >> 1][(nt & 1) * 2]);
        }

        __syncwarp();
#pragma unroll
        for (int mt = 0; mt < 2; mt++)
#pragma unroll
            for (int hh = 0; hh < 2; hh++) {
                float bm = -1e30f;
#pragma unroll
                for (int nt = 0; nt < 8; nt++) {
                    bm = fmaxf(bm, sacc[mt][nt][2 * hh]);
                    bm = fmaxf(bm, sacc[mt][nt][2 * hh + 1]);
                }
                bm = fmaxf(bm, __shfl_xor_sync(0xffffffffu, bm, 1));
                bm = fmaxf(bm, __shfl_xor_sync(0xffffffffu, bm, 2));
                float mn = fmaxf(mrow[mt][hh], bm);
                float scale = __expf(mrow[mt][hh] - mn);
                mrow[mt][hh] = mn;
                lrow[mt][hh] *= scale;
#pragma unroll
                for (int nt = 0; nt < 8; nt++) {
                    oacc[mt][nt][2 * hh]     *= scale;
                    oacc[mt][nt][2 * hh + 1] *= scale;
                }
                float psum = 0.f;
                int row = mt * 16 + gid + hh * 8;
#pragma unroll
                for (int nt = 0; nt < 8; nt++) {
                    float p0 = __expf(sacc[mt][nt][2 * hh]     - mn);
                    float p1 = __expf(sacc[mt][nt][2 * hh + 1] - mn);
                    psum += p0 + p1;
                    *(bf162*)(Pw + row * AST + nt * 8 + 2 * tig) =
                        __floats2bfloat162_rn(p0, p1);
                }
                psum += __shfl_xor_sync(0xffffffffu, psum, 1);
                psum += __shfl_xor_sync(0xffffffffu, psum, 2);
                lrow[mt][hh] += psum;
            }
        __syncwarp();

#pragma unroll
        for (int ks = 0; ks < 4; ks++) {
            uint32_t pf[2][4], vb4[4][4];
#pragma unroll
            for (int mt = 0; mt < 2; mt++)
                ldm_x4(pf[mt], PwB + (uint32_t)(((mt * 16 + (lane & 15)) * AST +
                         ks * 16 + (lane >> 4) * 8) * 2));
#pragma unroll
            for (int nb = 0; nb < 4; nb++)
                ldm_x4_t(vb4[nb], VbB + (uint32_t)(((jb * 64 + ks * 16 + vrow) * AST +
                           nb * 16 + vdim) * 2));
#pragma unroll
            for (int mt = 0; mt < 2; mt++)
#pragma unroll
                for (int nt = 0; nt < 8; nt++)
                    mma_bf16(oacc[mt][nt], pf[mt], &vb4[nt >> 1][(nt & 1) * 2]);
        }
    }

    const int win = wh / 6, head = wh % 6;
#pragma unroll
    for (int mt = 0; mt < 2; mt++)
#pragma unroll
        for (int hh = 0; hh < 2; hh++) {
            float inv = 1.0f / lrow[mt][hh];
            int row = qr + mt * 16 + gid + hh * 8;
            bf16* op = out + ((size_t)win * 256 + row) * CDIM + head * 64;
#pragma unroll
            for (int nt = 0; nt < 8; nt++) {
                bf162 o = __floats2bfloat162_rn(
                    oacc[mt][nt][2 * hh] * inv,
                    oacc[mt][nt][2 * hh + 1] * inv);
                *(bf162*)(op + nt * 8 + 2 * tig) = o;
            }
        }
}

// ---------------------------------------------------------------------------
extern "C" void kernel_launch(void* const* d_in, const int* in_sizes, int n_in,
                              void* d_out, int out_size) {
    (void)in_sizes; (void)n_in; (void)out_size;
    const float* x   = (const float*)d_in[0];
    const float* Wq  = (const float*)d_in[1];
    const float* bq  = (const float*)d_in[2];
    const float* Wk  = (const float*)d_in[3];
    const float* bk  = (const float*)d_in[4];
    const float* Wv  = (const float*)d_in[5];
    const float* bv  = (const float*)d_in[6];
    const float* Wo  = (const float*)d_in[7];
    const float* bo  = (const float*)d_in[8];
    const float* g1  = (const float*)d_in[9];
    const float* be1 = (const float*)d_in[10];
    const float* g2  = (const float*)d_in[11];
    const float* be2 = (const float*)d_in[12];
    const float* W1  = (const float*)d_in[13];
    const float* B1  = (const float*)d_in[14];
    const float* W2  = (const float*)d_in[15];
    const float* B2  = (const float*)d_in[16];
    float* out = (float*)d_out;

    float *x2;
    bf16 *hb, *qb, *kb, *vb, *att, *mlp, *wt;
    cudaGetSymbolAddress((void**)&hb,  g_h);
    cudaGetSymbolAddress((void**)&qb,  g_q);
    cudaGetSymbolAddress((void**)&kb,  g_k);
    cudaGetSymbolAddress((void**)&vb,  g_v);
    cudaGetSymbolAddress((void**)&att, g_att);
    cudaGetSymbolAddress((void**)&x2,  g_x2);
    cudaGetSymbolAddress((void**)&mlp, g_mlp);
    cudaGetSymbolAddress((void**)&wt,  g_wt);

    cudaFuncSetAttribute(ln1x_kernel,
                         cudaFuncAttributeMaxDynamicSharedMemorySize, LN1_SMEM);
    cudaFuncSetAttribute(attn_mma,
                         cudaFuncAttributeMaxDynamicSharedMemorySize, ATT_SMEM);
    cudaFuncSetAttribute(mm_qkv,
                         cudaFuncAttributeMaxDynamicSharedMemorySize, GSMEM);
    cudaFuncSetAttribute(mm_biasres_x,
                         cudaFuncAttributeMaxDynamicSharedMemorySize, GSMEM);
    cudaFuncSetAttribute(mm_biasres_scatter,
                         cudaFuncAttributeMaxDynamicSharedMemorySize, GSMEM);
    cudaFuncSetAttribute(mm_gelu,
                         cudaFuncAttributeMaxDynamicSharedMemorySize, GSMEM);

    // 1) fused shift + window-gather + LN1 -> hb bf16
    ln1x_kernel<<<dim3(2, 64, 16), 256, LN1_SMEM>>>(x, g1, be1, hb);
    // 2) QKV weight transpose
    transpose_qkv_kernel<<<dim3(12, 12, 3), 256>>>(Wq, Wk, Wv, wt);
    // 3) Wo transpose
    transpose_kernel<<<dim3(12, 12), 256>>>(Wo, wt + 442368, CDIM, CDIM);
    // 4) QKV projections (profiled launch)
    mm_qkv<<<dim3(3, 512, 3), 256, GSMEM>>>(hb, wt, bq, bk, bv, qb, kb, vb);
    // 5-6) MLP weight transposes
    transpose_kernel<<<dim3(48, 12), 256>>>(W1, wt + 589824,  CDIM, MLPD);
    transpose_kernel<<<dim3(12, 48), 256>>>(W2, wt + 1179648, MLPD, CDIM);
    // 7) windowed attention (bf16 flash)
    attn_mma<<<1536, 256, ATT_SMEM>>>(qb, kb, vb, att);
    // 8) output projection + bias + residual-from-x -> x2 fp32
    mm_biasres_x<<<dim3(3, 512), 256, GSMEM>>>(att, wt + 442368, bo, x, x2);
    // 9) LN2 -> bf16
    ln_kernel<<<8192, 256>>>(x2, g2, be2, hb);
    // 10) MLP up + GELU -> bf16
    mm_gelu<<<dim3(12, 512), 256, GSMEM>>>(hb, wt + 589824, B1, mlp);
    // 11) MLP down + residual + direct reverse-shift scatter -> out
    mm_biasres_scatter<<<dim3(3, 512), 256, GSMEM>>>(mlp, wt + 1179648, B2,
                                                     x2, out, MLPD);
}